// round 12
// baseline (speedup 1.0000x reference)
#include <cuda_runtime.h>
#include <cuda_bf16.h>
#include <cstdint>

#define Bq 2
#define Tq 4096
#define Cq 64
#define Hq 2
#define Kq 32
#define BHq 4
#define BTq 8192
#define CSq 8
#define NCH 512
#define Vq 32000

// ------------- scratch (static device globals; no allocation) -------------
__device__ __align__(16) float g_x [BTq*Cq];
__device__ __align__(16) float g_r [BHq*Tq*Kq];
__device__ __align__(16) float g_k [BHq*Tq*Kq];
__device__ __align__(16) float g_v [BHq*Tq*Kq];
__device__ __align__(16) float g_w [BHq*Tq*Kq];
__device__ __align__(16) float g_ol[BHq*Tq*Kq];
__device__ __align__(16) float g_rt[BHq*Tq*Kq];
__device__ __align__(16) float g_Tc[BHq*NCH*Kq*Kq];
__device__ __align__(16) float g_Wc[BHq*NCH*Kq];
__device__ __align__(16) float g_Sc[BHq*NCH*Kq*Kq];
__device__ __align__(16) __nv_bfloat16 g_xh[BTq*Cq];
__device__ __align__(16) __nv_bfloat16 g_xl[BTq*Cq];
__device__ __align__(16) __nv_bfloat16 g_eh[Vq*Cq];
__device__ __align__(16) __nv_bfloat16 g_el[Vq*Cq];

// ------------- mma / ldmatrix helpers -------------
#define MMA_BF16(c, a, b) \
    asm volatile( \
        "mma.sync.aligned.m16n8k16.row.col.f32.bf16.bf16.f32 " \
        "{%0,%1,%2,%3}, {%4,%5,%6,%7}, {%8,%9}, {%0,%1,%2,%3};" \
        : "+f"((c)[0]), "+f"((c)[1]), "+f"((c)[2]), "+f"((c)[3]) \
        : "r"((a)[0]), "r"((a)[1]), "r"((a)[2]), "r"((a)[3]), \
          "r"((b)[0]), "r"((b)[1]))

#define LDSM_X4(r0, r1, r2, r3, addr) \
    asm volatile( \
        "ldmatrix.sync.aligned.m8n8.x4.shared.b16 {%0,%1,%2,%3}, [%4];" \
        : "=r"(r0), "=r"(r1), "=r"(r2), "=r"(r3) : "r"(addr))

#define STG_CS_V2(ptr, vx, vy) \
    asm volatile("st.global.cs.v2.f32 [%0], {%1,%2};" \
                 :: "l"(ptr), "f"(vx), "f"(vy) : "memory")

#define CP_ASYNC16(smem_addr, gptr) \
    asm volatile("cp.async.ca.shared.global [%0], [%1], 16;" \
                 :: "r"(smem_addr), "l"(gptr) : "memory")

#define CP_COMMIT() asm volatile("cp.async.commit_group;" ::: "memory")
#define CP_WAIT0()  asm volatile("cp.async.wait_group 0;" ::: "memory")

__device__ __forceinline__ uint32_t smem_to_u32(const void* smem_ptr) {
    uint32_t addr;
    asm("{ .reg .u64 tmp; cvta.to.shared.u64 tmp, %1; cvt.u32.u64 %0, tmp; }"
        : "=r"(addr) : "l"(smem_ptr));
    return addr;
}

// ---------------- prep: embed hi/lo split + token gather (fused) ----------------
__global__ void prep_kernel(const int* __restrict__ tokens, const float* __restrict__ embed) {
    int blk = blockIdx.x;
    if (blk < 8000) {
        int i = blk * 256 + threadIdx.x;
        float v = embed[i];
        __nv_bfloat16 h = __float2bfloat16(v);
        g_eh[i] = h;
        g_el[i] = __float2bfloat16(v - __bfloat162float(h));
    } else {
        int i = (blk - 8000) * 256 + threadIdx.x;
        int row = i >> 6;
        int c = i & 63;
        g_x[i] = embed[(size_t)tokens[row] * Cq + c];
    }
}

// ---------------- r/k/v/w projections ----------------
__global__ void __launch_bounds__(256) proj_kernel(
    const float* __restrict__ Wr, const float* __restrict__ Wk,
    const float* __restrict__ Wv, const float* __restrict__ Ww) {
    __shared__ float xs[32 * 64];
    int tid = threadIdx.x;
    int r0 = blockIdx.x * 32;
    {
        const float4* s = reinterpret_cast<const float4*>(g_x + (size_t)r0 * Cq);
        float4* d = reinterpret_cast<float4*>(xs);
        d[tid] = s[tid];
        d[tid + 256] = s[tid + 256];
    }
    __syncthreads();
    int q = tid & 63;
    int rs = tid >> 6;
    int mat = q >> 4;
    int colm = (q & 15) << 2;
    const float* W = (mat == 0) ? Wr : ((mat == 1) ? Wk : ((mat == 2) ? Wv : Ww));
    float acc[8][4];
    #pragma unroll
    for (int r = 0; r < 8; r++) {
        acc[r][0] = 0.f; acc[r][1] = 0.f; acc[r][2] = 0.f; acc[r][3] = 0.f;
    }
    #pragma unroll
    for (int c4 = 0; c4 < 16; c4++) {
        float4 w0 = *reinterpret_cast<const float4*>(W + (c4 * 4 + 0) * 64 + colm);
        float4 w1 = *reinterpret_cast<const float4*>(W + (c4 * 4 + 1) * 64 + colm);
        float4 w2 = *reinterpret_cast<const float4*>(W + (c4 * 4 + 2) * 64 + colm);
        float4 w3 = *reinterpret_cast<const float4*>(W + (c4 * 4 + 3) * 64 + colm);
        #pragma unroll
        for (int r = 0; r < 8; r++) {
            float4 xv = *reinterpret_cast<const float4*>(xs + (rs * 8 + r) * 64 + c4 * 4);
            acc[r][0] = fmaf(xv.x, w0.x, fmaf(xv.y, w1.x, fmaf(xv.z, w2.x, fmaf(xv.w, w3.x, acc[r][0]))));
            acc[r][1] = fmaf(xv.x, w0.y, fmaf(xv.y, w1.y, fmaf(xv.z, w2.y, fmaf(xv.w, w3.y, acc[r][1]))));
            acc[r][2] = fmaf(xv.x, w0.z, fmaf(xv.y, w1.z, fmaf(xv.z, w2.z, fmaf(xv.w, w3.z, acc[r][2]))));
            acc[r][3] = fmaf(xv.x, w0.w, fmaf(xv.y, w1.w, fmaf(xv.z, w2.w, fmaf(xv.w, w3.w, acc[r][3]))));
        }
    }
    int h = colm >> 5;
    int kk = colm & 31;
    #pragma unroll
    for (int r = 0; r < 8; r++) {
        int row = r0 + rs * 8 + r;
        int b = row >> 12;
        int t = row & (Tq - 1);
        int idx = ((b * Hq + h) * Tq + t) * Kq + kk;
        float4 v;
        v.x = acc[r][0]; v.y = acc[r][1]; v.z = acc[r][2]; v.w = acc[r][3];
        if (mat == 3) {
            v.x = expf(-expf(v.x)); v.y = expf(-expf(v.y));
            v.z = expf(-expf(v.z)); v.w = expf(-expf(v.w));
            *reinterpret_cast<float4*>(g_w + idx) = v;
        } else if (mat == 0) {
            *reinterpret_cast<float4*>(g_r + idx) = v;
        } else if (mat == 1) {
            *reinterpret_cast<float4*>(g_k + idx) = v;
        } else {
            *reinterpret_cast<float4*>(g_v + idx) = v;
        }
    }
}

// ---------------- chunk-local scan: TWO warps per chunk (kk halves) ----------------
__global__ void __launch_bounds__(256) chunk_scan_kernel(const float* __restrict__ uL) {
    int wid = threadIdx.x >> 5;
    int lane = threadIdx.x & 31;
    int pair = wid >> 1;                 // chunk slot in block: 0..3
    int half = wid & 1;                  // kk half
    int g = blockIdx.x * 4 + pair;       // chunk id
    int bh = g / NCH;
    int c = g % NCH;
    int h = bh & 1;
    __shared__ float olp[4][CSq][32];

    float u = uL[h * Kq + lane];
    int kk0 = half * 16;
    float ub[16];
    #pragma unroll
    for (int i = 0; i < 16; i++) ub[i] = __shfl_sync(0xffffffffu, u, kk0 + i);
    float Z[16];
    #pragma unroll
    for (int i = 0; i < 16; i++) Z[i] = 0.f;
    float D = 1.f;
    float o0[CSq];

    int base = (bh * Tq + c * CSq) * Kq + lane;
    float rv = g_r[base];
    float kv = g_k[base];
    float vv = g_v[base];
    float wv = g_w[base];
    #pragma unroll
    for (int t = 0; t < CSq; t++) {
        float rn = 0.f, kn = 0.f, vn = 0.f, wn = 0.f;
        if (t + 1 < CSq) {
            int b2 = base + (t + 1) * Kq;
            rn = g_r[b2]; kn = g_k[b2]; vn = g_v[b2]; wn = g_w[b2];
        }
        if (half == 0) g_rt[base + t * Kq] = rv * D;
        float oa = 0.f, ob = 0.f;
        #pragma unroll
        for (int i = 0; i < 16; i += 2) {
            float rk0 = __shfl_sync(0xffffffffu, rv, kk0 + i);
            float kx0 = __shfl_sync(0xffffffffu, kv, kk0 + i);
            float wk0 = __shfl_sync(0xffffffffu, wv, kk0 + i);
            float rk1 = __shfl_sync(0xffffffffu, rv, kk0 + i + 1);
            float kx1 = __shfl_sync(0xffffffffu, kv, kk0 + i + 1);
            float wk1 = __shfl_sync(0xffffffffu, wv, kk0 + i + 1);
            float kvv0 = kx0 * vv;
            float kvv1 = kx1 * vv;
            oa = fmaf(rk0, fmaf(ub[i], kvv0, Z[i]), oa);
            ob = fmaf(rk1, fmaf(ub[i + 1], kvv1, Z[i + 1]), ob);
            Z[i]     = fmaf(wk0, Z[i], kvv0);
            Z[i + 1] = fmaf(wk1, Z[i + 1], kvv1);
        }
        float o = oa + ob;
        if (half == 1) olp[pair][t][lane] = o;
        else o0[t] = o;
        D *= wv;
        rv = rn; kv = kn; vv = vn; wv = wn;
    }
    // Tc / Wc
    int tb = ((bh * NCH + c) * Kq) * Kq + lane;
    #pragma unroll
    for (int i = 0; i < 16; i++) g_Tc[tb + (kk0 + i) * Kq] = Z[i];
    if (half == 0) g_Wc[(bh * NCH + c) * Kq + lane] = D;
    __syncthreads();
    if (half == 0) {
        #pragma unroll
        for (int t = 0; t < CSq; t++)
            g_ol[base + t * Kq] = o0[t] + olp[pair][t][lane];
    }
}

// ---------------- parallel affine-scan chunk combine ----------------
#define GC (NCH / 32)
__global__ void __launch_bounds__(1024) chunk_combine_kernel() {
    int blk = blockIdx.x;
    int bh = blk >> 5;
    int kk = blk & 31;
    int tid = threadIdx.x;
    int g = tid >> 5;
    int vv = tid & 31;

    float a[GC], b[GC];
    #pragma unroll
    for (int j = 0; j < GC; j++) {
        int c = g * GC + j;
        a[j] = g_Wc[(bh * NCH + c) * Kq + kk];
        b[j] = g_Tc[((bh * NCH + c) * Kq + kk) * Kq + vv];
    }
    float A = 1.f, Bv = 0.f;
    #pragma unroll
    for (int j = 0; j < GC; j++) {
        Bv = fmaf(a[j], Bv, b[j]);
        A *= a[j];
    }
    __shared__ float sA[32 * 32];
    __shared__ float sB[32 * 32];
    sA[g * 32 + vv] = A;
    sB[g * 32 + vv] = Bv;
    __syncthreads();
    #pragma unroll
    for (int d = 1; d < 32; d <<= 1) {
        float cA = sA[g * 32 + vv];
        float cB = sB[g * 32 + vv];
        float pA = 1.f, pB = 0.f;
        if (g >= d) {
            pA = sA[(g - d) * 32 + vv];
            pB = sB[(g - d) * 32 + vv];
        }
        __syncthreads();
        sA[g * 32 + vv] = cA * pA;
        sB[g * 32 + vv] = fmaf(cA, pB, cB);
        __syncthreads();
    }
    float s = (g == 0) ? 0.f : sB[(g - 1) * 32 + vv];
    #pragma unroll
    for (int j = 0; j < GC; j++) {
        int c = g * GC + j;
        g_Sc[((bh * NCH + c) * Kq + kk) * Kq + vv] = s;
        s = fmaf(a[j], s, b[j]);
    }
}

// ---------------- fused: o = ol + r~.Sc ; y = o@Wo ; x += y ; optional split ----------------
// block = (b, 32-row group). smem: Sc 8*4KB | Wo 16KB | o 8KB = 56KB
#define PS_TOT 57344
__global__ void __launch_bounds__(128) post_kernel(const float* __restrict__ Wo, int do_split) {
    extern __shared__ float ps[];
    float* Ss  = ps;            // 8 matrices x 1024 floats
    float* Wos = ps + 8192;     // 4096
    float* os  = ps + 12288;    // 2048
    int tid = threadIdx.x;
    int bb = blockIdx.x;
    int b = bb >> 7;
    int cg = bb & 127;
    int c0 = cg * 4;

    #pragma unroll
    for (int i = tid; i < 2048; i += 128) {
        int mi = i >> 8;       // matrix 0..7 : h = mi>>2, ci = mi&3
        int off = i & 255;
        int h = mi >> 2;
        int ci = mi & 3;
        int bh = b * 2 + h;
        const float4* src = reinterpret_cast<const float4*>(
            g_Sc + (size_t)(bh * NCH + c0 + ci) * 1024) + off;
        reinterpret_cast<float4*>(Ss + mi * 1024)[off] = *src;
    }
    #pragma unroll
    for (int i = tid; i < 1024; i += 128)
        reinterpret_cast<float4*>(Wos)[i] = reinterpret_cast<const float4*>(Wo)[i];
    __syncthreads();

    int w = tid >> 5;
    int lane = tid & 31;
    #pragma unroll
    for (int j = 0; j < 8; j++) {
        int r = w * 8 + j;     // 0..31
        int ci = r >> 3;
        int t = cg * 32 + r;
        #pragma unroll
        for (int h = 0; h < 2; h++) {
            int bh = b * 2 + h;
            int idx = (bh * Tq + t) * Kq + lane;
            float rv = g_rt[idx];
            float o = g_ol[idx];
            const float* S = Ss + (h * 4 + ci) * 1024;
            #pragma unroll
            for (int kk = 0; kk < 32; kk++) {
                float rk = __shfl_sync(0xffffffffu, rv, kk);
                o = fmaf(rk, S[kk * 32 + lane], o);
            }
            os[r * 64 + h * 32 + lane] = o;
        }
    }
    __syncthreads();

    int q = tid & 15;
    int rs = tid >> 4;          // 0..7
    int colm = q << 2;
    float acc[4][4];
    #pragma unroll
    for (int r = 0; r < 4; r++) {
        acc[r][0] = 0.f; acc[r][1] = 0.f; acc[r][2] = 0.f; acc[r][3] = 0.f;
    }
    #pragma unroll
    for (int c4 = 0; c4 < 16; c4++) {
        float4 w0 = *reinterpret_cast<const float4*>(Wos + (c4 * 4 + 0) * 64 + colm);
        float4 w1 = *reinterpret_cast<const float4*>(Wos + (c4 * 4 + 1) * 64 + colm);
        float4 w2 = *reinterpret_cast<const float4*>(Wos + (c4 * 4 + 2) * 64 + colm);
        float4 w3 = *reinterpret_cast<const float4*>(Wos + (c4 * 4 + 3) * 64 + colm);
        #pragma unroll
        for (int r = 0; r < 4; r++) {
            float4 xv = *reinterpret_cast<const float4*>(os + (rs * 4 + r) * 64 + c4 * 4);
            acc[r][0] = fmaf(xv.x, w0.x, fmaf(xv.y, w1.x, fmaf(xv.z, w2.x, fmaf(xv.w, w3.x, acc[r][0]))));
            acc[r][1] = fmaf(xv.x, w0.y, fmaf(xv.y, w1.y, fmaf(xv.z, w2.y, fmaf(xv.w, w3.y, acc[r][1]))));
            acc[r][2] = fmaf(xv.x, w0.z, fmaf(xv.y, w1.z, fmaf(xv.z, w2.z, fmaf(xv.w, w3.z, acc[r][2]))));
            acc[r][3] = fmaf(xv.x, w0.w, fmaf(xv.y, w1.w, fmaf(xv.z, w2.w, fmaf(xv.w, w3.w, acc[r][3]))));
        }
    }
    #pragma unroll
    for (int r = 0; r < 4; r++) {
        int row = b * Tq + cg * 32 + rs * 4 + r;
        size_t gidx = (size_t)row * Cq + colm;
        float4* px = reinterpret_cast<float4*>(g_x + gidx);
        float4 old = *px;
        old.x += acc[r][0]; old.y += acc[r][1]; old.z += acc[r][2]; old.w += acc[r][3];
        *px = old;
        if (do_split) {
            __nv_bfloat16 h0 = __float2bfloat16(old.x);
            __nv_bfloat16 h1 = __float2bfloat16(old.y);
            __nv_bfloat16 h2 = __float2bfloat16(old.z);
            __nv_bfloat16 h3 = __float2bfloat16(old.w);
            __nv_bfloat162 hh0; hh0.x = h0; hh0.y = h1;
            __nv_bfloat162 hh1; hh1.x = h2; hh1.y = h3;
            *reinterpret_cast<__nv_bfloat162*>(g_xh + gidx) = hh0;
            *reinterpret_cast<__nv_bfloat162*>(g_xh + gidx + 2) = hh1;
            __nv_bfloat162 ll0, ll1;
            ll0.x = __float2bfloat16(old.x - __bfloat162float(h0));
            ll0.y = __float2bfloat16(old.y - __bfloat162float(h1));
            ll1.x = __float2bfloat16(old.z - __bfloat162float(h2));
            ll1.y = __float2bfloat16(old.w - __bfloat162float(h3));
            *reinterpret_cast<__nv_bfloat162*>(g_xl + gidx) = ll0;
            *reinterpret_cast<__nv_bfloat162*>(g_xl + gidx + 2) = ll1;
        }
    }
}

// ---------------- head GEMM: 4000 tiles (125 n x 32 m) across 148 CTAs ----------------
#define HS_TOT 196608
#define NTILES 4000

__device__ __forceinline__ void head_copy_A(uint32_t sb, int tid, int buf, int m0) {
    uint32_t dst = sb + 65536u + (uint32_t)buf * 65536u;
    const __nv_bfloat16* srch = g_xh + (size_t)m0 * Cq;
    const __nv_bfloat16* srcl = g_xl + (size_t)m0 * Cq;
    #pragma unroll
    for (int i = tid; i < 2048; i += 512) {
        int row = i >> 3;
        int ch = i & 7;
        uint32_t dsw = (uint32_t)(row * 128 + ((ch ^ (row & 7)) << 4));
        CP_ASYNC16(dst + dsw, srch + row * Cq + ch * 8);
        CP_ASYNC16(dst + 32768u + dsw, srcl + row * Cq + ch * 8);
    }
    CP_COMMIT();
}

__global__ void __launch_bounds__(512, 1) head_kernel(float* __restrict__ out) {
    extern __shared__ char smem[];
    const int tid = threadIdx.x;
    const int w = tid >> 5;
    const int lane = tid & 31;
    const uint32_t sb = smem_to_u32(smem);

    const int start = (int)((long long)blockIdx.x * NTILES / 148);
    const int end   = (int)((long long)(blockIdx.x + 1) * NTILES / 148);
    if (start >= end) return;

    const int g8 = lane >> 2;
    const int tig = lane & 3;
    const int wm = w >> 1;
    const int wn = w & 1;
    const int rA = (lane < 16) ? lane : (lane - 16);
    const int cA = (lane >= 16) ? 1 : 0;
    const int rB = lane & 7;
    const int cB = lane >> 3;

    int curN = -1;
    head_copy_A(sb, tid, start & 1, (start & 31) * 256);

    for (int tau = start; tau < end; tau++) {
        int n = tau >> 5;
        int mt = tau & 31;
        if (n != curN) {
            __syncthreads();
            const int4* sB_h = reinterpret_cast<const int4*>(g_eh) + (size_t)n * 256 * 8;
            const int4* sB_l = reinterpret_cast<const int4*>(g_el) + (size_t)n * 256 * 8;
            #pragma unroll
            for (int i = tid; i < 2048; i += 512) {
                int row = i >> 3;
                int ch = i & 7;
                int dsw = row * 128 + ((ch ^ (row & 7)) << 4);
                *reinterpret_cast<int4*>(smem + dsw)         = sB_h[i];
                *reinterpret_cast<int4*>(smem + 32768 + dsw) = sB_l[i];
            }
            curN = n;
        }
        CP_WAIT0();
        __syncthreads();
        uint32_t abase = sb + 65536u + (uint32_t)((tau & 1) * 65536);

        uint32_t ah[2][4][4], al[2][4][4];
        #pragma unroll
        for (int mf = 0; mf < 2; mf++) {
            int row = wm * 32 + mf * 16 + rA;
            #pragma unroll
            for (int kc = 0; kc < 4; kc++) {
                int ch = kc * 2 + cA;
                uint32_t ad = abase + (uint32_t)(row * 128 + ((ch ^ (row & 7)) << 4));
                LDSM_X4(ah[mf][kc][0], ah[mf][kc][1], ah[mf][kc][2], ah[mf][kc][3], ad);
                LDSM_X4(al[mf][kc][0], al[mf][kc][1], al[mf][kc][2], al[mf][kc][3], ad + 32768u);
            }
        }
        if (tau + 1 < end) head_copy_A(sb, tid, (tau + 1) & 1, ((tau + 1) & 31) * 256);

        int n0 = n * 256;
        int m0 = mt * 256;
        #pragma unroll
        for (int nc = 0; nc < 16; nc++) {
            int nbase = wn * 128 + nc * 8;
            int rowB = nbase + rB;
            uint32_t bh[4][2], bl[4][2];
            #pragma unroll
            for (int p = 0; p < 2; p++) {
                int ch = p * 4 + cB;
                uint32_t ad = sb + (uint32_t)(rowB * 128 + ((ch ^ (rowB & 7)) << 4));
                LDSM_X4(bh[p * 2][0], bh[p * 2][1], bh[p * 2 + 1][0], bh[p * 2 + 1][1], ad);
                LDSM_X4(bl[p * 2][0], bl[p * 2][1], bl[p * 2 + 1][0], bl[p * 2 + 1][1], ad + 32768u);
            }
            float c0[4] = {0.f, 0.f, 0.f, 0.f};
            float c1[4] = {0.f, 0.f, 0.f, 0.f};
            #pragma unroll
            for (int kc = 0; kc < 4; kc++) {
                MMA_BF16(c0, ah[0][kc], bh[kc]);
                MMA_BF16(c0, ah[0][kc], bl[kc]);
                MMA_BF16(c0, al[0][kc], bh[kc]);
                MMA_BF16(c1, ah[1][kc], bh[kc]);
                MMA_BF16(c1, ah[1][kc], bl[kc]);
                MMA_BF16(c1, al[1][kc], bh[kc]);
            }
            size_t col = (size_t)(n0 + nbase + tig * 2);
            size_t r0g = (size_t)(m0 + wm * 32 + g8);
            float* p0 = out + r0g * Vq + col;
            STG_CS_V2(p0, c0[0], c0[1]);
            STG_CS_V2(p0 + 8 * (size_t)Vq, c0[2], c0[3]);
            STG_CS_V2(p0 + 16 * (size_t)Vq, c1[0], c1[1]);
            STG_CS_V2(p0 + 24 * (size_t)Vq, c1[2], c1[3]);
        }
    }
}

extern "C" void kernel_launch(void* const* d_in, const int* in_sizes, int n_in,
                              void* d_out, int out_size) {
    const int* tokens = (const int*)d_in[0];
    const float* embed = (const float*)d_in[1];
    const float* Wr = (const float*)d_in[2];
    const float* Wk = (const float*)d_in[3];
    const float* Wv = (const float*)d_in[4];
    const float* Ww = (const float*)d_in[5];
    const float* Wo = (const float*)d_in[6];
    const float* u = (const float*)d_in[7];
    float* out = (float*)d_out;

    prep_kernel<<<8000 + 2048, 256>>>(tokens, embed);
    cudaFuncSetAttribute(post_kernel, cudaFuncAttributeMaxDynamicSharedMemorySize, PS_TOT);
    for (int l = 0; l < 2; l++) {
        proj_kernel<<<256, 256>>>(Wr + l * 4096, Wk + l * 4096, Wv + l * 4096, Ww + l * 4096);
        chunk_scan_kernel<<<BHq * NCH / 4, 256>>>(u + l * Hq * Kq);
        chunk_combine_kernel<<<BHq * Kq, 1024>>>();
        post_kernel<<<256, 128, PS_TOT>>>(Wo + l * 4096, l == 1);
    }
    cudaFuncSetAttribute(head_kernel, cudaFuncAttributeMaxDynamicSharedMemorySize, HS_TOT);
    head_kernel<<<148, 512, HS_TOT>>>(out);
}

// round 13
// speedup vs baseline: 1.0384x; 1.0384x over previous
#include <cuda_runtime.h>
#include <cuda_bf16.h>
#include <cstdint>

#define Bq 2
#define Tq 4096
#define Cq 64
#define Hq 2
#define Kq 32
#define BHq 4
#define BTq 8192
#define CSq 8
#define NCH 512
#define Vq 32000

// ------------- scratch (static device globals; no allocation) -------------
__device__ __align__(16) float g_x [BTq*Cq];
__device__ __align__(16) float g_ol[BHq*Tq*Kq];
__device__ __align__(16) float g_rt[BHq*Tq*Kq];
__device__ __align__(16) float g_Tc[BHq*NCH*Kq*Kq];
__device__ __align__(16) float g_Wc[BHq*NCH*Kq];
__device__ __align__(16) float g_Sc[BHq*NCH*Kq*Kq];
__device__ __align__(16) __nv_bfloat16 g_xh[BTq*Cq];
__device__ __align__(16) __nv_bfloat16 g_xl[BTq*Cq];
__device__ __align__(16) __nv_bfloat16 g_eh[Vq*Cq];
__device__ __align__(16) __nv_bfloat16 g_el[Vq*Cq];

// ------------- mma / ldmatrix helpers -------------
#define MMA_BF16(c, a, b) \
    asm volatile( \
        "mma.sync.aligned.m16n8k16.row.col.f32.bf16.bf16.f32 " \
        "{%0,%1,%2,%3}, {%4,%5,%6,%7}, {%8,%9}, {%0,%1,%2,%3};" \
        : "+f"((c)[0]), "+f"((c)[1]), "+f"((c)[2]), "+f"((c)[3]) \
        : "r"((a)[0]), "r"((a)[1]), "r"((a)[2]), "r"((a)[3]), \
          "r"((b)[0]), "r"((b)[1]))

#define LDSM_X4(r0, r1, r2, r3, addr) \
    asm volatile( \
        "ldmatrix.sync.aligned.m8n8.x4.shared.b16 {%0,%1,%2,%3}, [%4];" \
        : "=r"(r0), "=r"(r1), "=r"(r2), "=r"(r3) : "r"(addr))

#define STG_CS_V2(ptr, vx, vy) \
    asm volatile("st.global.cs.v2.f32 [%0], {%1,%2};" \
                 :: "l"(ptr), "f"(vx), "f"(vy) : "memory")

#define CP_ASYNC16(smem_addr, gptr) \
    asm volatile("cp.async.ca.shared.global [%0], [%1], 16;" \
                 :: "r"(smem_addr), "l"(gptr) : "memory")

#define CP_COMMIT() asm volatile("cp.async.commit_group;" ::: "memory")
#define CP_WAIT0()  asm volatile("cp.async.wait_group 0;" ::: "memory")

__device__ __forceinline__ uint32_t smem_to_u32(const void* smem_ptr) {
    uint32_t addr;
    asm("{ .reg .u64 tmp; cvta.to.shared.u64 tmp, %1; cvt.u32.u64 %0, tmp; }"
        : "=r"(addr) : "l"(smem_ptr));
    return addr;
}

// ---------------- prep: embed hi/lo split + token gather (fused) ----------------
__global__ void prep_kernel(const int* __restrict__ tokens, const float* __restrict__ embed) {
    int blk = blockIdx.x;
    if (blk < 8000) {
        int i = blk * 256 + threadIdx.x;
        float v = embed[i];
        __nv_bfloat16 h = __float2bfloat16(v);
        g_eh[i] = h;
        g_el[i] = __float2bfloat16(v - __bfloat162float(h));
    } else {
        int i = (blk - 8000) * 256 + threadIdx.x;
        int row = i >> 6;
        int c = i & 63;
        g_x[i] = embed[(size_t)tokens[row] * Cq + c];
    }
}

// ---------------- fused proj + chunk scan ----------------
// block: 32 consecutive tokens of one b. Phase 1: r/k/v/w into smem.
// Phase 2: warp w -> chunk ci = w>>1, head h = w&1; scan over 8 steps,
// per-kk scalars read via conflict-free smem broadcast.
__global__ void __launch_bounds__(256) proj_scan_kernel(
    const float* __restrict__ Wr, const float* __restrict__ Wk,
    const float* __restrict__ Wv, const float* __restrict__ Ww,
    const float* __restrict__ uL) {
    __shared__ float xs[32 * 64];
    __shared__ float sm_r[32 * 64];
    __shared__ float sm_k[32 * 64];
    __shared__ float sm_v[32 * 64];
    __shared__ float sm_w[32 * 64];
    int tid = threadIdx.x;
    int r0 = blockIdx.x * 32;
    {
        const float4* s = reinterpret_cast<const float4*>(g_x + (size_t)r0 * Cq);
        float4* d = reinterpret_cast<float4*>(xs);
        d[tid] = s[tid];
        d[tid + 256] = s[tid + 256];
    }
    __syncthreads();
    {
        int q = tid & 63;
        int rs = tid >> 6;
        int mat = q >> 4;
        int colm = (q & 15) << 2;
        const float* W = (mat == 0) ? Wr : ((mat == 1) ? Wk : ((mat == 2) ? Wv : Ww));
        float* dst = (mat == 0) ? sm_r : ((mat == 1) ? sm_k : ((mat == 2) ? sm_v : sm_w));
        float acc[8][4];
        #pragma unroll
        for (int r = 0; r < 8; r++) {
            acc[r][0] = 0.f; acc[r][1] = 0.f; acc[r][2] = 0.f; acc[r][3] = 0.f;
        }
        #pragma unroll
        for (int c4 = 0; c4 < 16; c4++) {
            float4 w0 = *reinterpret_cast<const float4*>(W + (c4 * 4 + 0) * 64 + colm);
            float4 w1 = *reinterpret_cast<const float4*>(W + (c4 * 4 + 1) * 64 + colm);
            float4 w2 = *reinterpret_cast<const float4*>(W + (c4 * 4 + 2) * 64 + colm);
            float4 w3 = *reinterpret_cast<const float4*>(W + (c4 * 4 + 3) * 64 + colm);
            #pragma unroll
            for (int r = 0; r < 8; r++) {
                float4 xv = *reinterpret_cast<const float4*>(xs + (rs * 8 + r) * 64 + c4 * 4);
                acc[r][0] = fmaf(xv.x, w0.x, fmaf(xv.y, w1.x, fmaf(xv.z, w2.x, fmaf(xv.w, w3.x, acc[r][0]))));
                acc[r][1] = fmaf(xv.x, w0.y, fmaf(xv.y, w1.y, fmaf(xv.z, w2.y, fmaf(xv.w, w3.y, acc[r][1]))));
                acc[r][2] = fmaf(xv.x, w0.z, fmaf(xv.y, w1.z, fmaf(xv.z, w2.z, fmaf(xv.w, w3.z, acc[r][2]))));
                acc[r][3] = fmaf(xv.x, w0.w, fmaf(xv.y, w1.w, fmaf(xv.z, w2.w, fmaf(xv.w, w3.w, acc[r][3]))));
            }
        }
        #pragma unroll
        for (int r = 0; r < 8; r++) {
            float4 v;
            v.x = acc[r][0]; v.y = acc[r][1]; v.z = acc[r][2]; v.w = acc[r][3];
            if (mat == 3) {
                v.x = expf(-expf(v.x)); v.y = expf(-expf(v.y));
                v.z = expf(-expf(v.z)); v.w = expf(-expf(v.w));
            }
            *reinterpret_cast<float4*>(dst + (rs * 8 + r) * 64 + colm) = v;
        }
    }
    __syncthreads();

    // phase 2: scan. warp -> (chunk ci, head h)
    int w = tid >> 5;
    int lane = tid & 31;
    int ci = w >> 1;
    int h = w & 1;
    int b = r0 >> 12;
    int bh = b * Hq + h;
    int tloc = r0 & (Tq - 1);
    int c = (tloc >> 3) + ci;            // global chunk index (CSq=8)
    int col = h * 32;

    float ub[Kq];
    #pragma unroll
    for (int kk = 0; kk < Kq; kk++) ub[kk] = uL[col + kk];
    float Z[Kq];
    #pragma unroll
    for (int i = 0; i < Kq; i++) Z[i] = 0.f;
    float D = 1.f;
    int base = (bh * Tq + tloc + ci * CSq) * Kq + lane;

    #pragma unroll
    for (int t = 0; t < CSq; t++) {
        const float* rrow = sm_r + (ci * 8 + t) * 64 + col;
        const float* krow = sm_k + (ci * 8 + t) * 64 + col;
        const float* wrow = sm_w + (ci * 8 + t) * 64 + col;
        float vvv = sm_v[(ci * 8 + t) * 64 + col + lane];
        float rl = rrow[lane];
        float wl = wrow[lane];
        g_rt[base + t * Kq] = rl * D;
        float o0 = 0.f, o1 = 0.f;
        #pragma unroll
        for (int kk = 0; kk < Kq; kk += 2) {
            float rk0 = rrow[kk];
            float kx0 = krow[kk];
            float wk0 = wrow[kk];
            float rk1 = rrow[kk + 1];
            float kx1 = krow[kk + 1];
            float wk1 = wrow[kk + 1];
            float kvv0 = kx0 * vvv;
            float kvv1 = kx1 * vvv;
            o0 = fmaf(rk0, fmaf(ub[kk], kvv0, Z[kk]), o0);
            o1 = fmaf(rk1, fmaf(ub[kk + 1], kvv1, Z[kk + 1]), o1);
            Z[kk]     = fmaf(wk0, Z[kk], kvv0);
            Z[kk + 1] = fmaf(wk1, Z[kk + 1], kvv1);
        }
        g_ol[base + t * Kq] = o0 + o1;
        D *= wl;
    }
    g_Wc[(bh * NCH + c) * Kq + lane] = D;
    int tb = ((bh * NCH + c) * Kq) * Kq + lane;
    #pragma unroll
    for (int kk = 0; kk < Kq; kk++) g_Tc[tb + kk * Kq] = Z[kk];
}

// ---------------- parallel affine-scan chunk combine ----------------
#define GC (NCH / 32)
__global__ void __launch_bounds__(1024) chunk_combine_kernel() {
    int blk = blockIdx.x;
    int bh = blk >> 5;
    int kk = blk & 31;
    int tid = threadIdx.x;
    int g = tid >> 5;
    int vv = tid & 31;

    float a[GC], b[GC];
    #pragma unroll
    for (int j = 0; j < GC; j++) {
        int c = g * GC + j;
        a[j] = g_Wc[(bh * NCH + c) * Kq + kk];
        b[j] = g_Tc[((bh * NCH + c) * Kq + kk) * Kq + vv];
    }
    float A = 1.f, Bv = 0.f;
    #pragma unroll
    for (int j = 0; j < GC; j++) {
        Bv = fmaf(a[j], Bv, b[j]);
        A *= a[j];
    }
    __shared__ float sA[32 * 32];
    __shared__ float sB[32 * 32];
    sA[g * 32 + vv] = A;
    sB[g * 32 + vv] = Bv;
    __syncthreads();
    #pragma unroll
    for (int d = 1; d < 32; d <<= 1) {
        float cA = sA[g * 32 + vv];
        float cB = sB[g * 32 + vv];
        float pA = 1.f, pB = 0.f;
        if (g >= d) {
            pA = sA[(g - d) * 32 + vv];
            pB = sB[(g - d) * 32 + vv];
        }
        __syncthreads();
        sA[g * 32 + vv] = cA * pA;
        sB[g * 32 + vv] = fmaf(cA, pB, cB);
        __syncthreads();
    }
    float s = (g == 0) ? 0.f : sB[(g - 1) * 32 + vv];
    #pragma unroll
    for (int j = 0; j < GC; j++) {
        int c = g * GC + j;
        g_Sc[((bh * NCH + c) * Kq + kk) * Kq + vv] = s;
        s = fmaf(a[j], s, b[j]);
    }
}

// ---------------- fused: o = ol + r~.Sc ; y = o@Wo ; x += y ; optional split ----------------
// block = (b, 64-row group). smem: Sc 16*4KB | Wo 16KB | o 16KB  = 96KB (R11 form)
#define PS_TOT 98304
__global__ void __launch_bounds__(256) post_kernel(const float* __restrict__ Wo, int do_split) {
    extern __shared__ float ps[];
    float* Ss  = ps;            // 16 matrices x 1024 floats
    float* Wos = ps + 16384;    // 4096
    float* os  = ps + 20480;    // 4096
    int tid = threadIdx.x;
    int bb = blockIdx.x;
    int b = bb >> 6;
    int cg = bb & 63;
    int c0 = cg * 8;

    #pragma unroll
    for (int i = tid; i < 4096; i += 256) {
        int mi = i >> 8;
        int off = i & 255;
        int h = mi >> 3;
        int ci = mi & 7;
        int bh = b * 2 + h;
        const float4* src = reinterpret_cast<const float4*>(
            g_Sc + (size_t)(bh * NCH + c0 + ci) * 1024) + off;
        reinterpret_cast<float4*>(Ss + mi * 1024)[off] = *src;
    }
    #pragma unroll
    for (int i = tid; i < 1024; i += 256)
        reinterpret_cast<float4*>(Wos)[i] = reinterpret_cast<const float4*>(Wo)[i];
    __syncthreads();

    int w = tid >> 5;
    int lane = tid & 31;
    #pragma unroll
    for (int j = 0; j < 8; j++) {
        int r = w * 8 + j;
        int ci = r >> 3;
        int t = cg * 64 + r;
        #pragma unroll
        for (int h = 0; h < 2; h++) {
            int bh = b * 2 + h;
            int idx = (bh * Tq + t) * Kq + lane;
            float rv = g_rt[idx];
            float o = g_ol[idx];
            const float* S = Ss + (h * 8 + ci) * 1024;
            #pragma unroll
            for (int kk = 0; kk < 32; kk++) {
                float rk = __shfl_sync(0xffffffffu, rv, kk);
                o = fmaf(rk, S[kk * 32 + lane], o);
            }
            os[r * 64 + h * 32 + lane] = o;
        }
    }
    __syncthreads();

    int q = tid & 15;
    int rs = tid >> 4;
    int colm = q << 2;
    float acc[4][4];
    #pragma unroll
    for (int r = 0; r < 4; r++) {
        acc[r][0] = 0.f; acc[r][1] = 0.f; acc[r][2] = 0.f; acc[r][3] = 0.f;
    }
    #pragma unroll
    for (int c4 = 0; c4 < 16; c4++) {
        float4 w0 = *reinterpret_cast<const float4*>(Wos + (c4 * 4 + 0) * 64 + colm);
        float4 w1 = *reinterpret_cast<const float4*>(Wos + (c4 * 4 + 1) * 64 + colm);
        float4 w2 = *reinterpret_cast<const float4*>(Wos + (c4 * 4 + 2) * 64 + colm);
        float4 w3 = *reinterpret_cast<const float4*>(Wos + (c4 * 4 + 3) * 64 + colm);
        #pragma unroll
        for (int r = 0; r < 4; r++) {
            float4 xv = *reinterpret_cast<const float4*>(os + (rs * 4 + r) * 64 + c4 * 4);
            acc[r][0] = fmaf(xv.x, w0.x, fmaf(xv.y, w1.x, fmaf(xv.z, w2.x, fmaf(xv.w, w3.x, acc[r][0]))));
            acc[r][1] = fmaf(xv.x, w0.y, fmaf(xv.y, w1.y, fmaf(xv.z, w2.y, fmaf(xv.w, w3.y, acc[r][1]))));
            acc[r][2] = fmaf(xv.x, w0.z, fmaf(xv.y, w1.z, fmaf(xv.z, w2.z, fmaf(xv.w, w3.z, acc[r][2]))));
            acc[r][3] = fmaf(xv.x, w0.w, fmaf(xv.y, w1.w, fmaf(xv.z, w2.w, fmaf(xv.w, w3.w, acc[r][3]))));
        }
    }
    #pragma unroll
    for (int r = 0; r < 4; r++) {
        int row = b * Tq + cg * 64 + rs * 4 + r;
        size_t gidx = (size_t)row * Cq + colm;
        float4* px = reinterpret_cast<float4*>(g_x + gidx);
        float4 old = *px;
        old.x += acc[r][0]; old.y += acc[r][1]; old.z += acc[r][2]; old.w += acc[r][3];
        *px = old;
        if (do_split) {
            __nv_bfloat16 h0 = __float2bfloat16(old.x);
            __nv_bfloat16 h1 = __float2bfloat16(old.y);
            __nv_bfloat16 h2 = __float2bfloat16(old.z);
            __nv_bfloat16 h3 = __float2bfloat16(old.w);
            __nv_bfloat162 hh0; hh0.x = h0; hh0.y = h1;
            __nv_bfloat162 hh1; hh1.x = h2; hh1.y = h3;
            *reinterpret_cast<__nv_bfloat162*>(g_xh + gidx) = hh0;
            *reinterpret_cast<__nv_bfloat162*>(g_xh + gidx + 2) = hh1;
            __nv_bfloat162 ll0, ll1;
            ll0.x = __float2bfloat16(old.x - __bfloat162float(h0));
            ll0.y = __float2bfloat16(old.y - __bfloat162float(h1));
            ll1.x = __float2bfloat16(old.z - __bfloat162float(h2));
            ll1.y = __float2bfloat16(old.w - __bfloat162float(h3));
            *reinterpret_cast<__nv_bfloat162*>(g_xl + gidx) = ll0;
            *reinterpret_cast<__nv_bfloat162*>(g_xl + gidx + 2) = ll1;
        }
    }
}

// ---------------- head GEMM: 4000 tiles (125 n x 32 m) across 148 CTAs ----------------
#define HS_TOT 196608
#define NTILES 4000

__device__ __forceinline__ void head_copy_A(uint32_t sb, int tid, int buf, int m0) {
    uint32_t dst = sb + 65536u + (uint32_t)buf * 65536u;
    const __nv_bfloat16* srch = g_xh + (size_t)m0 * Cq;
    const __nv_bfloat16* srcl = g_xl + (size_t)m0 * Cq;
    #pragma unroll
    for (int i = tid; i < 2048; i += 512) {
        int row = i >> 3;
        int ch = i & 7;
        uint32_t dsw = (uint32_t)(row * 128 + ((ch ^ (row & 7)) << 4));
        CP_ASYNC16(dst + dsw, srch + row * Cq + ch * 8);
        CP_ASYNC16(dst + 32768u + dsw, srcl + row * Cq + ch * 8);
    }
    CP_COMMIT();
}

__global__ void __launch_bounds__(512, 1) head_kernel(float* __restrict__ out) {
    extern __shared__ char smem[];
    const int tid = threadIdx.x;
    const int w = tid >> 5;
    const int lane = tid & 31;
    const uint32_t sb = smem_to_u32(smem);

    const int start = (int)((long long)blockIdx.x * NTILES / 148);
    const int end   = (int)((long long)(blockIdx.x + 1) * NTILES / 148);
    if (start >= end) return;

    const int g8 = lane >> 2;
    const int tig = lane & 3;
    const int wm = w >> 1;
    const int wn = w & 1;
    const int rA = (lane < 16) ? lane : (lane - 16);
    const int cA = (lane >= 16) ? 1 : 0;
    const int rB = lane & 7;
    const int cB = lane >> 3;

    int curN = -1;
    head_copy_A(sb, tid, start & 1, (start & 31) * 256);

    for (int tau = start; tau < end; tau++) {
        int n = tau >> 5;
        int mt = tau & 31;
        if (n != curN) {
            __syncthreads();
            const int4* sB_h = reinterpret_cast<const int4*>(g_eh) + (size_t)n * 256 * 8;
            const int4* sB_l = reinterpret_cast<const int4*>(g_el) + (size_t)n * 256 * 8;
            #pragma unroll
            for (int i = tid; i < 2048; i += 512) {
                int row = i >> 3;
                int ch = i & 7;
                int dsw = row * 128 + ((ch ^ (row & 7)) << 4);
                *reinterpret_cast<int4*>(smem + dsw)         = sB_h[i];
                *reinterpret_cast<int4*>(smem + 32768 + dsw) = sB_l[i];
            }
            curN = n;
        }
        CP_WAIT0();
        __syncthreads();
        uint32_t abase = sb + 65536u + (uint32_t)((tau & 1) * 65536);

        uint32_t ah[2][4][4], al[2][4][4];
        #pragma unroll
        for (int mf = 0; mf < 2; mf++) {
            int row = wm * 32 + mf * 16 + rA;
            #pragma unroll
            for (int kc = 0; kc < 4; kc++) {
                int ch = kc * 2 + cA;
                uint32_t ad = abase + (uint32_t)(row * 128 + ((ch ^ (row & 7)) << 4));
                LDSM_X4(ah[mf][kc][0], ah[mf][kc][1], ah[mf][kc][2], ah[mf][kc][3], ad);
                LDSM_X4(al[mf][kc][0], al[mf][kc][1], al[mf][kc][2], al[mf][kc][3], ad + 32768u);
            }
        }
        if (tau + 1 < end) head_copy_A(sb, tid, (tau + 1) & 1, ((tau + 1) & 31) * 256);

        int n0 = n * 256;
        int m0 = mt * 256;
        #pragma unroll
        for (int nc = 0; nc < 16; nc++) {
            int nbase = wn * 128 + nc * 8;
            int rowB = nbase + rB;
            uint32_t bh[4][2], bl[4][2];
            #pragma unroll
            for (int p = 0; p < 2; p++) {
                int ch = p * 4 + cB;
                uint32_t ad = sb + (uint32_t)(rowB * 128 + ((ch ^ (rowB & 7)) << 4));
                LDSM_X4(bh[p * 2][0], bh[p * 2][1], bh[p * 2 + 1][0], bh[p * 2 + 1][1], ad);
                LDSM_X4(bl[p * 2][0], bl[p * 2][1], bl[p * 2 + 1][0], bl[p * 2 + 1][1], ad + 32768u);
            }
            float c0[4] = {0.f, 0.f, 0.f, 0.f};
            float c1[4] = {0.f, 0.f, 0.f, 0.f};
            #pragma unroll
            for (int kc = 0; kc < 4; kc++) {
                MMA_BF16(c0, ah[0][kc], bh[kc]);
                MMA_BF16(c0, ah[0][kc], bl[kc]);
                MMA_BF16(c0, al[0][kc], bh[kc]);
                MMA_BF16(c1, ah[1][kc], bh[kc]);
                MMA_BF16(c1, ah[1][kc], bl[kc]);
                MMA_BF16(c1, al[1][kc], bh[kc]);
            }
            size_t col = (size_t)(n0 + nbase + tig * 2);
            size_t r0g = (size_t)(m0 + wm * 32 + g8);
            float* p0 = out + r0g * Vq + col;
            STG_CS_V2(p0, c0[0], c0[1]);
            STG_CS_V2(p0 + 8 * (size_t)Vq, c0[2], c0[3]);
            STG_CS_V2(p0 + 16 * (size_t)Vq, c1[0], c1[1]);
            STG_CS_V2(p0 + 24 * (size_t)Vq, c1[2], c1[3]);
        }
    }
}

extern "C" void kernel_launch(void* const* d_in, const int* in_sizes, int n_in,
                              void* d_out, int out_size) {
    const int* tokens = (const int*)d_in[0];
    const float* embed = (const float*)d_in[1];
    const float* Wr = (const float*)d_in[2];
    const float* Wk = (const float*)d_in[3];
    const float* Wv = (const float*)d_in[4];
    const float* Ww = (const float*)d_in[5];
    const float* Wo = (const float*)d_in[6];
    const float* u = (const float*)d_in[7];
    float* out = (float*)d_out;

    prep_kernel<<<8000 + 2048, 256>>>(tokens, embed);
    cudaFuncSetAttribute(post_kernel, cudaFuncAttributeMaxDynamicSharedMemorySize, PS_TOT);
    for (int l = 0; l < 2; l++) {
        proj_scan_kernel<<<256, 256>>>(Wr + l * 4096, Wk + l * 4096, Wv + l * 4096,
                                       Ww + l * 4096, u + l * Hq * Kq);
        chunk_combine_kernel<<<BHq * Kq, 1024>>>();
        post_kernel<<<128, 256, PS_TOT>>>(Wo + l * 4096, l == 1);
    }
    cudaFuncSetAttribute(head_kernel, cudaFuncAttributeMaxDynamicSharedMemorySize, HS_TOT);
    head_kernel<<<148, 512, HS_TOT>>>(out);
}

// round 14
// speedup vs baseline: 1.1747x; 1.1312x over previous
#include <cuda_runtime.h>
#include <cuda_fp16.h>
#include <cuda_bf16.h>
#include <cstdint>

#define Bq 2
#define Tq 4096
#define Cq 64
#define Hq 2
#define Kq 32
#define BHq 4
#define BTq 8192
#define CSq 8
#define NCH 512
#define Vq 32000

// ------------- scratch (static device globals; no allocation) -------------
__device__ __align__(16) float g_x [BTq*Cq];
__device__ __align__(16) float g_ol[BHq*Tq*Kq];
__device__ __align__(16) float g_rt[BHq*Tq*Kq];
__device__ __align__(16) float g_Tc[BHq*NCH*Kq*Kq];
__device__ __align__(16) float g_Wc[BHq*NCH*Kq];
__device__ __align__(16) float g_Sc[BHq*NCH*Kq*Kq];
__device__ __align__(16) __half g_xh[BTq*Cq];
__device__ __align__(16) __half g_xl[BTq*Cq];
__device__ __align__(16) __half g_eh[Vq*Cq];

// ------------- mma / ldmatrix helpers -------------
#define MMA_FP16(c, a, b) \
    asm volatile( \
        "mma.sync.aligned.m16n8k16.row.col.f32.f16.f16.f32 " \
        "{%0,%1,%2,%3}, {%4,%5,%6,%7}, {%8,%9}, {%0,%1,%2,%3};" \
        : "+f"((c)[0]), "+f"((c)[1]), "+f"((c)[2]), "+f"((c)[3]) \
        : "r"((a)[0]), "r"((a)[1]), "r"((a)[2]), "r"((a)[3]), \
          "r"((b)[0]), "r"((b)[1]))

#define LDSM_X4(r0, r1, r2, r3, addr) \
    asm volatile( \
        "ldmatrix.sync.aligned.m8n8.x4.shared.b16 {%0,%1,%2,%3}, [%4];" \
        : "=r"(r0), "=r"(r1), "=r"(r2), "=r"(r3) : "r"(addr))

#define STG_CS_V2(ptr, vx, vy) \
    asm volatile("st.global.cs.v2.f32 [%0], {%1,%2};" \
                 :: "l"(ptr), "f"(vx), "f"(vy) : "memory")

#define CP_ASYNC16(smem_addr, gptr) \
    asm volatile("cp.async.ca.shared.global [%0], [%1], 16;" \
                 :: "r"(smem_addr), "l"(gptr) : "memory")

#define CP_COMMIT() asm volatile("cp.async.commit_group;" ::: "memory")
#define CP_WAIT0()  asm volatile("cp.async.wait_group 0;" ::: "memory")

__device__ __forceinline__ uint32_t smem_to_u32(const void* smem_ptr) {
    uint32_t addr;
    asm("{ .reg .u64 tmp; cvta.to.shared.u64 tmp, %1; cvt.u32.u64 %0, tmp; }"
        : "=r"(addr) : "l"(smem_ptr));
    return addr;
}

// ---------------- prep: embed fp16 convert + token gather (fused) ----------------
__global__ void prep_kernel(const int* __restrict__ tokens, const float* __restrict__ embed) {
    int blk = blockIdx.x;
    if (blk < 8000) {
        int i = blk * 256 + threadIdx.x;
        g_eh[i] = __float2half(embed[i]);
    } else {
        int i = (blk - 8000) * 256 + threadIdx.x;
        int row = i >> 6;
        int c = i & 63;
        g_x[i] = embed[(size_t)tokens[row] * Cq + c];
    }
}

// ---------------- fused proj + chunk scan ----------------
__global__ void __launch_bounds__(256) proj_scan_kernel(
    const float* __restrict__ Wr, const float* __restrict__ Wk,
    const float* __restrict__ Wv, const float* __restrict__ Ww,
    const float* __restrict__ uL) {
    __shared__ float xs[32 * 64];
    __shared__ float sm_r[32 * 64];
    __shared__ float sm_k[32 * 64];
    __shared__ float sm_v[32 * 64];
    __shared__ float sm_w[32 * 64];
    int tid = threadIdx.x;
    int r0 = blockIdx.x * 32;
    {
        const float4* s = reinterpret_cast<const float4*>(g_x + (size_t)r0 * Cq);
        float4* d = reinterpret_cast<float4*>(xs);
        d[tid] = s[tid];
        d[tid + 256] = s[tid + 256];
    }
    __syncthreads();
    {
        int q = tid & 63;
        int rs = tid >> 6;
        int mat = q >> 4;
        int colm = (q & 15) << 2;
        const float* W = (mat == 0) ? Wr : ((mat == 1) ? Wk : ((mat == 2) ? Wv : Ww));
        float* dst = (mat == 0) ? sm_r : ((mat == 1) ? sm_k : ((mat == 2) ? sm_v : sm_w));
        float acc[8][4];
        #pragma unroll
        for (int r = 0; r < 8; r++) {
            acc[r][0] = 0.f; acc[r][1] = 0.f; acc[r][2] = 0.f; acc[r][3] = 0.f;
        }
        #pragma unroll
        for (int c4 = 0; c4 < 16; c4++) {
            float4 w0 = *reinterpret_cast<const float4*>(W + (c4 * 4 + 0) * 64 + colm);
            float4 w1 = *reinterpret_cast<const float4*>(W + (c4 * 4 + 1) * 64 + colm);
            float4 w2 = *reinterpret_cast<const float4*>(W + (c4 * 4 + 2) * 64 + colm);
            float4 w3 = *reinterpret_cast<const float4*>(W + (c4 * 4 + 3) * 64 + colm);
            #pragma unroll
            for (int r = 0; r < 8; r++) {
                float4 xv = *reinterpret_cast<const float4*>(xs + (rs * 8 + r) * 64 + c4 * 4);
                acc[r][0] = fmaf(xv.x, w0.x, fmaf(xv.y, w1.x, fmaf(xv.z, w2.x, fmaf(xv.w, w3.x, acc[r][0]))));
                acc[r][1] = fmaf(xv.x, w0.y, fmaf(xv.y, w1.y, fmaf(xv.z, w2.y, fmaf(xv.w, w3.y, acc[r][1]))));
                acc[r][2] = fmaf(xv.x, w0.z, fmaf(xv.y, w1.z, fmaf(xv.z, w2.z, fmaf(xv.w, w3.z, acc[r][2]))));
                acc[r][3] = fmaf(xv.x, w0.w, fmaf(xv.y, w1.w, fmaf(xv.z, w2.w, fmaf(xv.w, w3.w, acc[r][3]))));
            }
        }
        #pragma unroll
        for (int r = 0; r < 8; r++) {
            float4 v;
            v.x = acc[r][0]; v.y = acc[r][1]; v.z = acc[r][2]; v.w = acc[r][3];
            if (mat == 3) {
                v.x = expf(-expf(v.x)); v.y = expf(-expf(v.y));
                v.z = expf(-expf(v.z)); v.w = expf(-expf(v.w));
            }
            *reinterpret_cast<float4*>(dst + (rs * 8 + r) * 64 + colm) = v;
        }
    }
    __syncthreads();

    int w = tid >> 5;
    int lane = tid & 31;
    int ci = w >> 1;
    int h = w & 1;
    int b = r0 >> 12;
    int bh = b * Hq + h;
    int tloc = r0 & (Tq - 1);
    int c = (tloc >> 3) + ci;
    int col = h * 32;

    float ub[Kq];
    #pragma unroll
    for (int kk = 0; kk < Kq; kk++) ub[kk] = uL[col + kk];
    float Z[Kq];
    #pragma unroll
    for (int i = 0; i < Kq; i++) Z[i] = 0.f;
    float D = 1.f;
    int base = (bh * Tq + tloc + ci * CSq) * Kq + lane;

    #pragma unroll
    for (int t = 0; t < CSq; t++) {
        const float* rrow = sm_r + (ci * 8 + t) * 64 + col;
        const float* krow = sm_k + (ci * 8 + t) * 64 + col;
        const float* wrow = sm_w + (ci * 8 + t) * 64 + col;
        float vvv = sm_v[(ci * 8 + t) * 64 + col + lane];
        float rl = rrow[lane];
        float wl = wrow[lane];
        g_rt[base + t * Kq] = rl * D;
        float o0 = 0.f, o1 = 0.f;
        #pragma unroll
        for (int kk = 0; kk < Kq; kk += 2) {
            float rk0 = rrow[kk];
            float kx0 = krow[kk];
            float wk0 = wrow[kk];
            float rk1 = rrow[kk + 1];
            float kx1 = krow[kk + 1];
            float wk1 = wrow[kk + 1];
            float kvv0 = kx0 * vvv;
            float kvv1 = kx1 * vvv;
            o0 = fmaf(rk0, fmaf(ub[kk], kvv0, Z[kk]), o0);
            o1 = fmaf(rk1, fmaf(ub[kk + 1], kvv1, Z[kk + 1]), o1);
            Z[kk]     = fmaf(wk0, Z[kk], kvv0);
            Z[kk + 1] = fmaf(wk1, Z[kk + 1], kvv1);
        }
        g_ol[base + t * Kq] = o0 + o1;
        D *= wl;
    }
    g_Wc[(bh * NCH + c) * Kq + lane] = D;
    int tb = ((bh * NCH + c) * Kq) * Kq + lane;
    #pragma unroll
    for (int kk = 0; kk < Kq; kk++) g_Tc[tb + kk * Kq] = Z[kk];
}

// ---------------- parallel affine-scan chunk combine ----------------
#define GC (NCH / 32)
__global__ void __launch_bounds__(1024) chunk_combine_kernel() {
    int blk = blockIdx.x;
    int bh = blk >> 5;
    int kk = blk & 31;
    int tid = threadIdx.x;
    int g = tid >> 5;
    int vv = tid & 31;

    float a[GC], b[GC];
    #pragma unroll
    for (int j = 0; j < GC; j++) {
        int c = g * GC + j;
        a[j] = g_Wc[(bh * NCH + c) * Kq + kk];
        b[j] = g_Tc[((bh * NCH + c) * Kq + kk) * Kq + vv];
    }
    float A = 1.f, Bv = 0.f;
    #pragma unroll
    for (int j = 0; j < GC; j++) {
        Bv = fmaf(a[j], Bv, b[j]);
        A *= a[j];
    }
    __shared__ float sA[32 * 32];
    __shared__ float sB[32 * 32];
    sA[g * 32 + vv] = A;
    sB[g * 32 + vv] = Bv;
    __syncthreads();
    #pragma unroll
    for (int d = 1; d < 32; d <<= 1) {
        float cA = sA[g * 32 + vv];
        float cB = sB[g * 32 + vv];
        float pA = 1.f, pB = 0.f;
        if (g >= d) {
            pA = sA[(g - d) * 32 + vv];
            pB = sB[(g - d) * 32 + vv];
        }
        __syncthreads();
        sA[g * 32 + vv] = cA * pA;
        sB[g * 32 + vv] = fmaf(cA, pB, cB);
        __syncthreads();
    }
    float s = (g == 0) ? 0.f : sB[(g - 1) * 32 + vv];
    #pragma unroll
    for (int j = 0; j < GC; j++) {
        int c = g * GC + j;
        g_Sc[((bh * NCH + c) * Kq + kk) * Kq + vv] = s;
        s = fmaf(a[j], s, b[j]);
    }
}

// ---------------- fused: o = ol + r~.Sc ; y = o@Wo ; x += y ; optional fp16 split ----------------
// block = (b, 64-row group), 512 threads. smem: Sc 64KB | Wo 16KB | o 16KB = 96KB
#define PS_TOT 98304
__global__ void __launch_bounds__(512) post_kernel(const float* __restrict__ Wo, int do_split) {
    extern __shared__ float ps[];
    float* Ss  = ps;            // 16 matrices x 1024 floats
    float* Wos = ps + 16384;    // 4096
    float* os  = ps + 20480;    // 4096
    int tid = threadIdx.x;
    int bb = blockIdx.x;
    int b = bb >> 6;
    int cg = bb & 63;
    int c0 = cg * 8;

    #pragma unroll
    for (int i = tid; i < 4096; i += 512) {
        int mi = i >> 8;
        int off = i & 255;
        int h = mi >> 3;
        int ci = mi & 7;
        int bh = b * 2 + h;
        const float4* src = reinterpret_cast<const float4*>(
            g_Sc + (size_t)(bh * NCH + c0 + ci) * 1024) + off;
        reinterpret_cast<float4*>(Ss + mi * 1024)[off] = *src;
    }
    #pragma unroll
    for (int i = tid; i < 1024; i += 512)
        reinterpret_cast<float4*>(Wos)[i] = reinterpret_cast<const float4*>(Wo)[i];
    __syncthreads();

    int w = tid >> 5;        // 0..15
    int lane = tid & 31;
    #pragma unroll
    for (int j = 0; j < 4; j++) {
        int r = w * 4 + j;   // 0..63
        int ci = r >> 3;
        int t = cg * 64 + r;
        #pragma unroll
        for (int h = 0; h < 2; h++) {
            int bh = b * 2 + h;
            int idx = (bh * Tq + t) * Kq + lane;
            float rv = g_rt[idx];
            float o = g_ol[idx];
            const float* S = Ss + (h * 8 + ci) * 1024;
            #pragma unroll
            for (int kk = 0; kk < 32; kk++) {
                float rk = __shfl_sync(0xffffffffu, rv, kk);
                o = fmaf(rk, S[kk * 32 + lane], o);
            }
            os[r * 64 + h * 32 + lane] = o;
        }
    }
    __syncthreads();

    int q = tid & 15;
    int rs = tid >> 4;       // 0..31
    int colm = q << 2;
    float acc[2][4];
    #pragma unroll
    for (int r = 0; r < 2; r++) {
        acc[r][0] = 0.f; acc[r][1] = 0.f; acc[r][2] = 0.f; acc[r][3] = 0.f;
    }
    #pragma unroll
    for (int c4 = 0; c4 < 16; c4++) {
        float4 w0 = *reinterpret_cast<const float4*>(Wos + (c4 * 4 + 0) * 64 + colm);
        float4 w1 = *reinterpret_cast<const float4*>(Wos + (c4 * 4 + 1) * 64 + colm);
        float4 w2 = *reinterpret_cast<const float4*>(Wos + (c4 * 4 + 2) * 64 + colm);
        float4 w3 = *reinterpret_cast<const float4*>(Wos + (c4 * 4 + 3) * 64 + colm);
        #pragma unroll
        for (int r = 0; r < 2; r++) {
            float4 xv = *reinterpret_cast<const float4*>(os + (rs * 2 + r) * 64 + c4 * 4);
            acc[r][0] = fmaf(xv.x, w0.x, fmaf(xv.y, w1.x, fmaf(xv.z, w2.x, fmaf(xv.w, w3.x, acc[r][0]))));
            acc[r][1] = fmaf(xv.x, w0.y, fmaf(xv.y, w1.y, fmaf(xv.z, w2.y, fmaf(xv.w, w3.y, acc[r][1]))));
            acc[r][2] = fmaf(xv.x, w0.z, fmaf(xv.y, w1.z, fmaf(xv.z, w2.z, fmaf(xv.w, w3.z, acc[r][2]))));
            acc[r][3] = fmaf(xv.x, w0.w, fmaf(xv.y, w1.w, fmaf(xv.z, w2.w, fmaf(xv.w, w3.w, acc[r][3]))));
        }
    }
    #pragma unroll
    for (int r = 0; r < 2; r++) {
        int row = b * Tq + cg * 64 + rs * 2 + r;
        size_t gidx = (size_t)row * Cq + colm;
        float4* px = reinterpret_cast<float4*>(g_x + gidx);
        float4 old = *px;
        old.x += acc[r][0]; old.y += acc[r][1]; old.z += acc[r][2]; old.w += acc[r][3];
        *px = old;
        if (do_split) {
            __half h0 = __float2half(old.x);
            __half h1 = __float2half(old.y);
            __half h2 = __float2half(old.z);
            __half h3 = __float2half(old.w);
            __half2 hh0; hh0.x = h0; hh0.y = h1;
            __half2 hh1; hh1.x = h2; hh1.y = h3;
            *reinterpret_cast<__half2*>(g_xh + gidx) = hh0;
            *reinterpret_cast<__half2*>(g_xh + gidx + 2) = hh1;
            __half2 ll0, ll1;
            ll0.x = __float2half(old.x - __half2float(h0));
            ll0.y = __float2half(old.y - __half2float(h1));
            ll1.x = __float2half(old.z - __half2float(h2));
            ll1.y = __float2half(old.w - __half2float(h3));
            *reinterpret_cast<__half2*>(g_xl + gidx) = ll0;
            *reinterpret_cast<__half2*>(g_xl + gidx + 2) = ll1;
        }
    }
}

// ---------------- head GEMM: fp16 2-product, 4000 tiles across 148 CTAs ----------------
// smem: B(eh) [0,32K) | A buf0 [32K,96K) (ah,al) | A buf1 [96K,160K)
#define HS_TOT 163840
#define NTILES 4000

__device__ __forceinline__ void head_copy_A(uint32_t sb, int tid, int buf, int m0) {
    uint32_t dst = sb + 32768u + (uint32_t)buf * 65536u;
    const __half* srch = g_xh + (size_t)m0 * Cq;
    const __half* srcl = g_xl + (size_t)m0 * Cq;
    #pragma unroll
    for (int i = tid; i < 2048; i += 512) {
        int row = i >> 3;
        int ch = i & 7;
        uint32_t dsw = (uint32_t)(row * 128 + ((ch ^ (row & 7)) << 4));
        CP_ASYNC16(dst + dsw, srch + row * Cq + ch * 8);
        CP_ASYNC16(dst + 32768u + dsw, srcl + row * Cq + ch * 8);
    }
    CP_COMMIT();
}

__global__ void __launch_bounds__(512, 1) head_kernel(float* __restrict__ out) {
    extern __shared__ char smem[];
    const int tid = threadIdx.x;
    const int w = tid >> 5;
    const int lane = tid & 31;
    const uint32_t sb = smem_to_u32(smem);

    const int start = (int)((long long)blockIdx.x * NTILES / 148);
    const int end   = (int)((long long)(blockIdx.x + 1) * NTILES / 148);
    if (start >= end) return;

    const int g8 = lane >> 2;
    const int tig = lane & 3;
    const int wm = w >> 1;
    const int wn = w & 1;
    const int rA = (lane < 16) ? lane : (lane - 16);
    const int cA = (lane >= 16) ? 1 : 0;
    const int rB = lane & 7;
    const int cB = lane >> 3;

    int curN = -1;
    head_copy_A(sb, tid, start & 1, (start & 31) * 256);

    for (int tau = start; tau < end; tau++) {
        int n = tau >> 5;
        int mt = tau & 31;
        if (n != curN) {
            __syncthreads();
            const int4* sB_h = reinterpret_cast<const int4*>(g_eh) + (size_t)n * 256 * 8;
            #pragma unroll
            for (int i = tid; i < 2048; i += 512) {
                int row = i >> 3;
                int ch = i & 7;
                int dsw = row * 128 + ((ch ^ (row & 7)) << 4);
                *reinterpret_cast<int4*>(smem + dsw) = sB_h[i];
            }
            curN = n;
        }
        CP_WAIT0();
        __syncthreads();
        uint32_t abase = sb + 32768u + (uint32_t)((tau & 1) * 65536);

        uint32_t ah[2][4][4], al[2][4][4];
        #pragma unroll
        for (int mf = 0; mf < 2; mf++) {
            int row = wm * 32 + mf * 16 + rA;
            #pragma unroll
            for (int kc = 0; kc < 4; kc++) {
                int ch = kc * 2 + cA;
                uint32_t ad = abase + (uint32_t)(row * 128 + ((ch ^ (row & 7)) << 4));
                LDSM_X4(ah[mf][kc][0], ah[mf][kc][1], ah[mf][kc][2], ah[mf][kc][3], ad);
                LDSM_X4(al[mf][kc][0], al[mf][kc][1], al[mf][kc][2], al[mf][kc][3], ad + 32768u);
            }
        }
        if (tau + 1 < end) head_copy_A(sb, tid, (tau + 1) & 1, ((tau + 1) & 31) * 256);

        int n0 = n * 256;
        int m0 = mt * 256;
        #pragma unroll
        for (int nc = 0; nc < 16; nc++) {
            int nbase = wn * 128 + nc * 8;
            int rowB = nbase + rB;
            uint32_t bh[4][2];
            #pragma unroll
            for (int p = 0; p < 2; p++) {
                int ch = p * 4 + cB;
                uint32_t ad = sb + (uint32_t)(rowB * 128 + ((ch ^ (rowB & 7)) << 4));
                LDSM_X4(bh[p * 2][0], bh[p * 2][1], bh[p * 2 + 1][0], bh[p * 2 + 1][1], ad);
            }
            float c0[4] = {0.f, 0.f, 0.f, 0.f};
            float c1[4] = {0.f, 0.f, 0.f, 0.f};
            #pragma unroll
            for (int kc = 0; kc < 4; kc++) {
                MMA_FP16(c0, ah[0][kc], bh[kc]);
                MMA_FP16(c0, al[0][kc], bh[kc]);
                MMA_FP16(c1, ah[1][kc], bh[kc]);
                MMA_FP16(c1, al[1][kc], bh[kc]);
            }
            size_t col = (size_t)(n0 + nbase + tig * 2);
            size_t r0g = (size_t)(m0 + wm * 32 + g8);
            float* p0 = out + r0g * Vq + col;
            STG_CS_V2(p0, c0[0], c0[1]);
            STG_CS_V2(p0 + 8 * (size_t)Vq, c0[2], c0[3]);
            STG_CS_V2(p0 + 16 * (size_t)Vq, c1[0], c1[1]);
            STG_CS_V2(p0 + 24 * (size_t)Vq, c1[2], c1[3]);
        }
    }
}

extern "C" void kernel_launch(void* const* d_in, const int* in_sizes, int n_in,
                              void* d_out, int out_size) {
    const int* tokens = (const int*)d_in[0];
    const float* embed = (const float*)d_in[1];
    const float* Wr = (const float*)d_in[2];
    const float* Wk = (const float*)d_in[3];
    const float* Wv = (const float*)d_in[4];
    const float* Ww = (const float*)d_in[5];
    const float* Wo = (const float*)d_in[6];
    const float* u = (const float*)d_in[7];
    float* out = (float*)d_out;

    prep_kernel<<<8000 + 2048, 256>>>(tokens, embed);
    cudaFuncSetAttribute(post_kernel, cudaFuncAttributeMaxDynamicSharedMemorySize, PS_TOT);
    for (int l = 0; l < 2; l++) {
        proj_scan_kernel<<<256, 256>>>(Wr + l * 4096, Wk + l * 4096, Wv + l * 4096,
                                       Ww + l * 4096, u + l * Hq * Kq);
        chunk_combine_kernel<<<BHq * Kq, 1024>>>();
        post_kernel<<<128, 512, PS_TOT>>>(Wo + l * 4096, l == 1);
    }
    cudaFuncSetAttribute(head_kernel, cudaFuncAttributeMaxDynamicSharedMemorySize, HS_TOT);
    head_kernel<<<148, 512, HS_TOT>>>(out);
}

// round 16
// speedup vs baseline: 1.2077x; 1.0281x over previous
#include <cuda_runtime.h>
#include <cuda_fp16.h>
#include <cstdint>

#define Bq 2
#define Tq 4096
#define Cq 64
#define Hq 2
#define Kq 32
#define BHq 4
#define BTq 8192
#define CSq 8
#define NCH 512
#define Vq 32000

// ------------- scratch (static device globals; no allocation) -------------
__device__ __align__(16) float g_x [BTq*Cq];
__device__ __align__(16) float g_ol[BHq*Tq*Kq];
__device__ __align__(16) float g_rt[BHq*Tq*Kq];
__device__ __align__(16) float g_Tc[BHq*NCH*Kq*Kq];
__device__ __align__(16) float g_Wc[BHq*NCH*Kq];
__device__ __align__(16) float g_Sc[BHq*NCH*Kq*Kq];
__device__ __align__(16) __half g_xh[BTq*Cq];
__device__ __align__(16) __half g_eh[Vq*Cq];

// ------------- mma / ldmatrix helpers -------------
#define MMA_FP16(c, a, b) \
    asm volatile( \
        "mma.sync.aligned.m16n8k16.row.col.f32.f16.f16.f32 " \
        "{%0,%1,%2,%3}, {%4,%5,%6,%7}, {%8,%9}, {%0,%1,%2,%3};" \
        : "+f"((c)[0]), "+f"((c)[1]), "+f"((c)[2]), "+f"((c)[3]) \
        : "r"((a)[0]), "r"((a)[1]), "r"((a)[2]), "r"((a)[3]), \
          "r"((b)[0]), "r"((b)[1]))

#define LDSM_X4(r0, r1, r2, r3, addr) \
    asm volatile( \
        "ldmatrix.sync.aligned.m8n8.x4.shared.b16 {%0,%1,%2,%3}, [%4];" \
        : "=r"(r0), "=r"(r1), "=r"(r2), "=r"(r3) : "r"(addr))

#define STG_CS_V2(ptr, vx, vy) \
    asm volatile("st.global.cs.v2.f32 [%0], {%1,%2};" \
                 :: "l"(ptr), "f"(vx), "f"(vy) : "memory")

#define CP_ASYNC16(smem_addr, gptr) \
    asm volatile("cp.async.ca.shared.global [%0], [%1], 16;" \
                 :: "r"(smem_addr), "l"(gptr) : "memory")

#define CP_COMMIT() asm volatile("cp.async.commit_group;" ::: "memory")
#define CP_WAIT0()  asm volatile("cp.async.wait_group 0;" ::: "memory")

__device__ __forceinline__ uint32_t smem_to_u32(const void* smem_ptr) {
    uint32_t addr;
    asm("{ .reg .u64 tmp; cvta.to.shared.u64 tmp, %1; cvt.u32.u64 %0, tmp; }"
        : "=r"(addr) : "l"(smem_ptr));
    return addr;
}

// ---------------- prep: embed fp16 convert + token gather (fused) ----------------
__global__ void prep_kernel(const int* __restrict__ tokens, const float* __restrict__ embed) {
    int blk = blockIdx.x;
    if (blk < 8000) {
        int i = blk * 256 + threadIdx.x;
        g_eh[i] = __float2half(embed[i]);
    } else {
        int i = (blk - 8000) * 256 + threadIdx.x;
        int row = i >> 6;
        int c = i & 63;
        g_x[i] = embed[(size_t)tokens[row] * Cq + c];
    }
}

// ---------------- fused proj + chunk scan ----------------
__global__ void __launch_bounds__(256) proj_scan_kernel(
    const float* __restrict__ Wr, const float* __restrict__ Wk,
    const float* __restrict__ Wv, const float* __restrict__ Ww,
    const float* __restrict__ uL) {
    __shared__ float xs[32 * 64];
    __shared__ float sm_r[32 * 64];
    __shared__ float sm_k[32 * 64];
    __shared__ float sm_v[32 * 64];
    __shared__ float sm_w[32 * 64];
    int tid = threadIdx.x;
    int r0 = blockIdx.x * 32;
    {
        const float4* s = reinterpret_cast<const float4*>(g_x + (size_t)r0 * Cq);
        float4* d = reinterpret_cast<float4*>(xs);
        d[tid] = s[tid];
        d[tid + 256] = s[tid + 256];
    }
    __syncthreads();
    {
        int q = tid & 63;
        int rs = tid >> 6;
        int mat = q >> 4;
        int colm = (q & 15) << 2;
        const float* W = (mat == 0) ? Wr : ((mat == 1) ? Wk : ((mat == 2) ? Wv : Ww));
        float* dst = (mat == 0) ? sm_r : ((mat == 1) ? sm_k : ((mat == 2) ? sm_v : sm_w));
        float acc[8][4];
        #pragma unroll
        for (int r = 0; r < 8; r++) {
            acc[r][0] = 0.f; acc[r][1] = 0.f; acc[r][2] = 0.f; acc[r][3] = 0.f;
        }
        #pragma unroll
        for (int c4 = 0; c4 < 16; c4++) {
            float4 w0 = *reinterpret_cast<const float4*>(W + (c4 * 4 + 0) * 64 + colm);
            float4 w1 = *reinterpret_cast<const float4*>(W + (c4 * 4 + 1) * 64 + colm);
            float4 w2 = *reinterpret_cast<const float4*>(W + (c4 * 4 + 2) * 64 + colm);
            float4 w3 = *reinterpret_cast<const float4*>(W + (c4 * 4 + 3) * 64 + colm);
            #pragma unroll
            for (int r = 0; r < 8; r++) {
                float4 xv = *reinterpret_cast<const float4*>(xs + (rs * 8 + r) * 64 + c4 * 4);
                acc[r][0] = fmaf(xv.x, w0.x, fmaf(xv.y, w1.x, fmaf(xv.z, w2.x, fmaf(xv.w, w3.x, acc[r][0]))));
                acc[r][1] = fmaf(xv.x, w0.y, fmaf(xv.y, w1.y, fmaf(xv.z, w2.y, fmaf(xv.w, w3.y, acc[r][1]))));
                acc[r][2] = fmaf(xv.x, w0.z, fmaf(xv.y, w1.z, fmaf(xv.z, w2.z, fmaf(xv.w, w3.z, acc[r][2]))));
                acc[r][3] = fmaf(xv.x, w0.w, fmaf(xv.y, w1.w, fmaf(xv.z, w2.w, fmaf(xv.w, w3.w, acc[r][3]))));
            }
        }
        #pragma unroll
        for (int r = 0; r < 8; r++) {
            float4 v;
            v.x = acc[r][0]; v.y = acc[r][1]; v.z = acc[r][2]; v.w = acc[r][3];
            if (mat == 3) {
                v.x = expf(-expf(v.x)); v.y = expf(-expf(v.y));
                v.z = expf(-expf(v.z)); v.w = expf(-expf(v.w));
            }
            *reinterpret_cast<float4*>(dst + (rs * 8 + r) * 64 + colm) = v;
        }
    }
    __syncthreads();

    int w = tid >> 5;
    int lane = tid & 31;
    int ci = w >> 1;
    int h = w & 1;
    int b = r0 >> 12;
    int bh = b * Hq + h;
    int tloc = r0 & (Tq - 1);
    int c = (tloc >> 3) + ci;
    int col = h * 32;

    float ub[Kq];
    #pragma unroll
    for (int kk = 0; kk < Kq; kk++) ub[kk] = uL[col + kk];
    float Z[Kq];
    #pragma unroll
    for (int i = 0; i < Kq; i++) Z[i] = 0.f;
    float D = 1.f;
    int base = (bh * Tq + tloc + ci * CSq) * Kq + lane;

    #pragma unroll
    for (int t = 0; t < CSq; t++) {
        const float* rrow = sm_r + (ci * 8 + t) * 64 + col;
        const float* krow = sm_k + (ci * 8 + t) * 64 + col;
        const float* wrow = sm_w + (ci * 8 + t) * 64 + col;
        float vvv = sm_v[(ci * 8 + t) * 64 + col + lane];
        float rl = rrow[lane];
        float wl = wrow[lane];
        g_rt[base + t * Kq] = rl * D;
        float o0 = 0.f, o1 = 0.f;
        #pragma unroll
        for (int kk = 0; kk < Kq; kk += 2) {
            float rk0 = rrow[kk];
            float kx0 = krow[kk];
            float wk0 = wrow[kk];
            float rk1 = rrow[kk + 1];
            float kx1 = krow[kk + 1];
            float wk1 = wrow[kk + 1];
            float kvv0 = kx0 * vvv;
            float kvv1 = kx1 * vvv;
            o0 = fmaf(rk0, fmaf(ub[kk], kvv0, Z[kk]), o0);
            o1 = fmaf(rk1, fmaf(ub[kk + 1], kvv1, Z[kk + 1]), o1);
            Z[kk]     = fmaf(wk0, Z[kk], kvv0);
            Z[kk + 1] = fmaf(wk1, Z[kk + 1], kvv1);
        }
        g_ol[base + t * Kq] = o0 + o1;
        D *= wl;
    }
    g_Wc[(bh * NCH + c) * Kq + lane] = D;
    int tb = ((bh * NCH + c) * Kq) * Kq + lane;
    #pragma unroll
    for (int kk = 0; kk < Kq; kk++) g_Tc[tb + kk * Kq] = Z[kk];
}

// ---------------- parallel affine-scan chunk combine ----------------
#define GC (NCH / 32)
__global__ void __launch_bounds__(1024) chunk_combine_kernel() {
    int blk = blockIdx.x;
    int bh = blk >> 5;
    int kk = blk & 31;
    int tid = threadIdx.x;
    int g = tid >> 5;
    int vv = tid & 31;

    float a[GC], b[GC];
    #pragma unroll
    for (int j = 0; j < GC; j++) {
        int c = g * GC + j;
        a[j] = g_Wc[(bh * NCH + c) * Kq + kk];
        b[j] = g_Tc[((bh * NCH + c) * Kq + kk) * Kq + vv];
    }
    float A = 1.f, Bv = 0.f;
    #pragma unroll
    for (int j = 0; j < GC; j++) {
        Bv = fmaf(a[j], Bv, b[j]);
        A *= a[j];
    }
    __shared__ float sA[32 * 32];
    __shared__ float sB[32 * 32];
    sA[g * 32 + vv] = A;
    sB[g * 32 + vv] = Bv;
    __syncthreads();
    #pragma unroll
    for (int d = 1; d < 32; d <<= 1) {
        float cA = sA[g * 32 + vv];
        float cB = sB[g * 32 + vv];
        float pA = 1.f, pB = 0.f;
        if (g >= d) {
            pA = sA[(g - d) * 32 + vv];
            pB = sB[(g - d) * 32 + vv];
        }
        __syncthreads();
        sA[g * 32 + vv] = cA * pA;
        sB[g * 32 + vv] = fmaf(cA, pB, cB);
        __syncthreads();
    }
    float s = (g == 0) ? 0.f : sB[(g - 1) * 32 + vv];
    #pragma unroll
    for (int j = 0; j < GC; j++) {
        int c = g * GC + j;
        g_Sc[((bh * NCH + c) * Kq + kk) * Kq + vv] = s;
        s = fmaf(a[j], s, b[j]);
    }
}

// ---------------- fused: o = ol + r~.Sc ; y = o@Wo ; x += y ; optional fp16 ----------------
// block = (b, 64-row group), 512 threads, 16 warps; warp -> (chunk ci, head h).
// S register-resident (32/lane). smem: Wo 16KB + o 16KB = 32KB.
__global__ void __launch_bounds__(512) post_kernel(const float* __restrict__ Wo, int do_split) {
    __shared__ float Wos[4096];
    __shared__ float os[4096];
    int tid = threadIdx.x;
    int bb = blockIdx.x;
    int b = bb >> 6;
    int cg = bb & 63;
    int c0 = cg * 8;

    #pragma unroll
    for (int i = tid; i < 1024; i += 512)
        reinterpret_cast<float4*>(Wos)[i] = reinterpret_cast<const float4*>(Wo)[i];

    int w = tid >> 5;        // 0..15
    int lane = tid & 31;
    int ci = w >> 1;         // 0..7
    int h = w & 1;
    int bh = b * 2 + h;
    int c = c0 + ci;

    float S[32];
    {
        const float* Sp = g_Sc + (size_t)(bh * NCH + c) * 1024;
        #pragma unroll
        for (int kk = 0; kk < 32; kk++) S[kk] = Sp[kk * 32 + lane];
    }
    #pragma unroll
    for (int j = 0; j < 8; j++) {
        int r = ci * 8 + j;             // 0..63 within group
        int t = cg * 64 + r;
        int idx = (bh * Tq + t) * Kq + lane;
        float rv = g_rt[idx];
        float o = g_ol[idx];
        #pragma unroll
        for (int kk = 0; kk < 32; kk++) {
            float rk = __shfl_sync(0xffffffffu, rv, kk);
            o = fmaf(rk, S[kk], o);
        }
        os[r * 64 + h * 32 + lane] = o;
    }
    __syncthreads();

    int q = tid & 15;
    int rs = tid >> 4;       // 0..31
    int colm = q << 2;
    float acc[2][4];
    #pragma unroll
    for (int r = 0; r < 2; r++) {
        acc[r][0] = 0.f; acc[r][1] = 0.f; acc[r][2] = 0.f; acc[r][3] = 0.f;
    }
    #pragma unroll
    for (int c4 = 0; c4 < 16; c4++) {
        float4 w0 = *reinterpret_cast<const float4*>(Wos + (c4 * 4 + 0) * 64 + colm);
        float4 w1 = *reinterpret_cast<const float4*>(Wos + (c4 * 4 + 1) * 64 + colm);
        float4 w2 = *reinterpret_cast<const float4*>(Wos + (c4 * 4 + 2) * 64 + colm);
        float4 w3 = *reinterpret_cast<const float4*>(Wos + (c4 * 4 + 3) * 64 + colm);
        #pragma unroll
        for (int r = 0; r < 2; r++) {
            float4 xv = *reinterpret_cast<const float4*>(os + (rs * 2 + r) * 64 + c4 * 4);
            acc[r][0] = fmaf(xv.x, w0.x, fmaf(xv.y, w1.x, fmaf(xv.z, w2.x, fmaf(xv.w, w3.x, acc[r][0]))));
            acc[r][1] = fmaf(xv.x, w0.y, fmaf(xv.y, w1.y, fmaf(xv.z, w2.y, fmaf(xv.w, w3.y, acc[r][1]))));
            acc[r][2] = fmaf(xv.x, w0.z, fmaf(xv.y, w1.z, fmaf(xv.z, w2.z, fmaf(xv.w, w3.z, acc[r][2]))));
            acc[r][3] = fmaf(xv.x, w0.w, fmaf(xv.y, w1.w, fmaf(xv.z, w2.w, fmaf(xv.w, w3.w, acc[r][3]))));
        }
    }
    #pragma unroll
    for (int r = 0; r < 2; r++) {
        int row = b * Tq + cg * 64 + rs * 2 + r;
        size_t gidx = (size_t)row * Cq + colm;
        float4* px = reinterpret_cast<float4*>(g_x + gidx);
        float4 old = *px;
        old.x += acc[r][0]; old.y += acc[r][1]; old.z += acc[r][2]; old.w += acc[r][3];
        *px = old;
        if (do_split) {
            __half2 hh0; hh0.x = __float2half(old.x); hh0.y = __float2half(old.y);
            __half2 hh1; hh1.x = __float2half(old.z); hh1.y = __float2half(old.w);
            *reinterpret_cast<__half2*>(g_xh + gidx) = hh0;
            *reinterpret_cast<__half2*>(g_xh + gidx + 2) = hh1;
        }
    }
}

// ---------------- head GEMM: fp16 single-product, 4000 tiles across 148 CTAs ----------------
// smem: B(eh) [0,32K) | A buf0 [32K,64K) | A buf1 [64K,96K)
#define HS_TOT 98304
#define NTILES 4000

__device__ __forceinline__ void head_copy_A(uint32_t sb, int tid, int buf, int m0) {
    uint32_t dst = sb + 32768u + (uint32_t)buf * 32768u;
    const __half* srch = g_xh + (size_t)m0 * Cq;
    #pragma unroll
    for (int i = tid; i < 2048; i += 512) {
        int row = i >> 3;
        int ch = i & 7;
        uint32_t dsw = (uint32_t)(row * 128 + ((ch ^ (row & 7)) << 4));
        CP_ASYNC16(dst + dsw, srch + row * Cq + ch * 8);
    }
    CP_COMMIT();
}

__global__ void __launch_bounds__(512, 2) head_kernel(float* __restrict__ out) {
    extern __shared__ char smem[];
    const int tid = threadIdx.x;
    const int w = tid >> 5;
    const int lane = tid & 31;
    const uint32_t sb = smem_to_u32(smem);

    const int start = (int)((long long)blockIdx.x * NTILES / 148);
    const int end   = (int)((long long)(blockIdx.x + 1) * NTILES / 148);
    if (start >= end) return;

    const int g8 = lane >> 2;
    const int tig = lane & 3;
    const int wm = w >> 1;
    const int wn = w & 1;
    const int rA = (lane < 16) ? lane : (lane - 16);
    const int cA = (lane >= 16) ? 1 : 0;
    const int rB = lane & 7;
    const int cB = lane >> 3;

    int curN = -1;
    head_copy_A(sb, tid, start & 1, (start & 31) * 256);

    for (int tau = start; tau < end; tau++) {
        int n = tau >> 5;
        int mt = tau & 31;
        if (n != curN) {
            __syncthreads();
            const int4* sB_h = reinterpret_cast<const int4*>(g_eh) + (size_t)n * 256 * 8;
            #pragma unroll
            for (int i = tid; i < 2048; i += 512) {
                int row = i >> 3;
                int ch = i & 7;
                int dsw = row * 128 + ((ch ^ (row & 7)) << 4);
                *reinterpret_cast<int4*>(smem + dsw) = sB_h[i];
            }
            curN = n;
        }
        CP_WAIT0();
        __syncthreads();
        uint32_t abase = sb + 32768u + (uint32_t)((tau & 1) * 32768);

        uint32_t ah[2][4][4];
        #pragma unroll
        for (int mf = 0; mf < 2; mf++) {
            int row = wm * 32 + mf * 16 + rA;
            #pragma unroll
            for (int kc = 0; kc < 4; kc++) {
                int ch = kc * 2 + cA;
                uint32_t ad = abase + (uint32_t)(row * 128 + ((ch ^ (row & 7)) << 4));
                LDSM_X4(ah[mf][kc][0], ah[mf][kc][1], ah[mf][kc][2], ah[mf][kc][3], ad);
            }
        }
        if (tau + 1 < end) head_copy_A(sb, tid, (tau + 1) & 1, ((tau + 1) & 31) * 256);

        int n0 = n * 256;
        int m0 = mt * 256;
        #pragma unroll
        for (int nc = 0; nc < 16; nc++) {
            int nbase = wn * 128 + nc * 8;
            int rowB = nbase + rB;
            uint32_t bh[4][2];
            #pragma unroll
            for (int p = 0; p < 2; p++) {
                int ch = p * 4 + cB;
                uint32_t ad = sb + (uint32_t)(rowB * 128 + ((ch ^ (rowB & 7)) << 4));
                LDSM_X4(bh[p * 2][0], bh[p * 2][1], bh[p * 2 + 1][0], bh[p * 2 + 1][1], ad);
            }
            float c0[4] = {0.f, 0.f, 0.f, 0.f};
            float c1[4] = {0.f, 0.f, 0.f, 0.f};
            #pragma unroll
            for (int kc = 0; kc < 4; kc++) {
                MMA_FP16(c0, ah[0][kc], bh[kc]);
                MMA_FP16(c1, ah[1][kc], bh[kc]);
            }
            size_t col = (size_t)(n0 + nbase + tig * 2);
            size_t r0g = (size_t)(m0 + wm * 32 + g8);
            float* p0 = out + r0g * Vq + col;
            STG_CS_V2(p0, c0[0], c0[1]);
            STG_CS_V2(p0 + 8 * (size_t)Vq, c0[2], c0[3]);
            STG_CS_V2(p0 + 16 * (size_t)Vq, c1[0], c1[1]);
            STG_CS_V2(p0 + 24 * (size_t)Vq, c1[2], c1[3]);
        }
    }
}

extern "C" void kernel_launch(void* const* d_in, const int* in_sizes, int n_in,
                              void* d_out, int out_size) {
    const int* tokens = (const int*)d_in[0];
    const float* embed = (const float*)d_in[1];
    const float* Wr = (const float*)d_in[2];
    const float* Wk = (const float*)d_in[3];
    const float* Wv = (const float*)d_in[4];
    const float* Ww = (const float*)d_in[5];
    const float* Wo = (const float*)d_in[6];
    const float* u = (const float*)d_in[7];
    float* out = (float*)d_out;

    prep_kernel<<<8000 + 2048, 256>>>(tokens, embed);
    for (int l = 0; l < 2; l++) {
        proj_scan_kernel<<<256, 256>>>(Wr + l * 4096, Wk + l * 4096, Wv + l * 4096,
                                       Ww + l * 4096, u + l * Hq * Kq);
        chunk_combine_kernel<<<BHq * Kq, 1024>>>();
        post_kernel<<<128, 512>>>(Wo + l * 4096, l == 1);
    }
    cudaFuncSetAttribute(head_kernel, cudaFuncAttributeMaxDynamicSharedMemorySize, HS_TOT);
    head_kernel<<<148, 512, HS_TOT>>>(out);
}

// round 17
// speedup vs baseline: 1.2321x; 1.0202x over previous
#include <cuda_runtime.h>
#include <cuda_fp16.h>
#include <cstdint>

#define Bq 2
#define Tq 4096
#define Cq 64
#define Hq 2
#define Kq 32
#define BHq 4
#define BTq 8192
#define CSq 8
#define NCH 512
#define Vq 32000

// ------------- scratch (static device globals; no allocation) -------------
__device__ __align__(16) float g_x [BTq*Cq];
__device__ __align__(16) float g_ol[BHq*Tq*Kq];
__device__ __align__(16) float g_rt[BHq*Tq*Kq];
__device__ __align__(16) float g_Tc[BHq*NCH*Kq*Kq];
__device__ __align__(16) float g_Wc[BHq*NCH*Kq];
__device__ __align__(16) float g_Sc[BHq*NCH*Kq*Kq];
__device__ __align__(16) __half g_xh[BTq*Cq];
__device__ __align__(16) __half g_eh[Vq*Cq];

// ------------- mma / ldmatrix helpers -------------
#define MMA_FP16(c, a, b) \
    asm volatile( \
        "mma.sync.aligned.m16n8k16.row.col.f32.f16.f16.f32 " \
        "{%0,%1,%2,%3}, {%4,%5,%6,%7}, {%8,%9}, {%0,%1,%2,%3};" \
        : "+f"((c)[0]), "+f"((c)[1]), "+f"((c)[2]), "+f"((c)[3]) \
        : "r"((a)[0]), "r"((a)[1]), "r"((a)[2]), "r"((a)[3]), \
          "r"((b)[0]), "r"((b)[1]))

#define LDSM_X4(r0, r1, r2, r3, addr) \
    asm volatile( \
        "ldmatrix.sync.aligned.m8n8.x4.shared.b16 {%0,%1,%2,%3}, [%4];" \
        : "=r"(r0), "=r"(r1), "=r"(r2), "=r"(r3) : "r"(addr))

#define STG_CS_V2(ptr, vx, vy) \
    asm volatile("st.global.cs.v2.f32 [%0], {%1,%2};" \
                 :: "l"(ptr), "f"(vx), "f"(vy) : "memory")

#define CP_ASYNC16(smem_addr, gptr) \
    asm volatile("cp.async.ca.shared.global [%0], [%1], 16;" \
                 :: "r"(smem_addr), "l"(gptr) : "memory")

#define CP_COMMIT() asm volatile("cp.async.commit_group;" ::: "memory")
#define CP_WAIT0()  asm volatile("cp.async.wait_group 0;" ::: "memory")

__device__ __forceinline__ uint32_t smem_to_u32(const void* smem_ptr) {
    uint32_t addr;
    asm("{ .reg .u64 tmp; cvta.to.shared.u64 tmp, %1; cvt.u32.u64 %0, tmp; }"
        : "=r"(addr) : "l"(smem_ptr));
    return addr;
}

// ---------------- prep: embed fp16 convert + token gather (fused) ----------------
__global__ void prep_kernel(const int* __restrict__ tokens, const float* __restrict__ embed) {
    int blk = blockIdx.x;
    if (blk < 8000) {
        int i = blk * 256 + threadIdx.x;
        g_eh[i] = __float2half(embed[i]);
    } else {
        int i = (blk - 8000) * 256 + threadIdx.x;
        int row = i >> 6;
        int c = i & 63;
        g_x[i] = embed[(size_t)tokens[row] * Cq + c];
    }
}

// ---------------- fused proj + chunk scan ----------------
__global__ void __launch_bounds__(256) proj_scan_kernel(
    const float* __restrict__ Wr, const float* __restrict__ Wk,
    const float* __restrict__ Wv, const float* __restrict__ Ww,
    const float* __restrict__ uL) {
    __shared__ float xs[32 * 64];
    __shared__ float sm_r[32 * 64];
    __shared__ float sm_k[32 * 64];
    __shared__ float sm_v[32 * 64];
    __shared__ float sm_w[32 * 64];
    int tid = threadIdx.x;
    int r0 = blockIdx.x * 32;
    {
        const float4* s = reinterpret_cast<const float4*>(g_x + (size_t)r0 * Cq);
        float4* d = reinterpret_cast<float4*>(xs);
        d[tid] = s[tid];
        d[tid + 256] = s[tid + 256];
    }
    __syncthreads();
    {
        int q = tid & 63;
        int rs = tid >> 6;
        int mat = q >> 4;
        int colm = (q & 15) << 2;
        const float* W = (mat == 0) ? Wr : ((mat == 1) ? Wk : ((mat == 2) ? Wv : Ww));
        float* dst = (mat == 0) ? sm_r : ((mat == 1) ? sm_k : ((mat == 2) ? sm_v : sm_w));
        float acc[8][4];
        #pragma unroll
        for (int r = 0; r < 8; r++) {
            acc[r][0] = 0.f; acc[r][1] = 0.f; acc[r][2] = 0.f; acc[r][3] = 0.f;
        }
        #pragma unroll
        for (int c4 = 0; c4 < 16; c4++) {
            float4 w0 = *reinterpret_cast<const float4*>(W + (c4 * 4 + 0) * 64 + colm);
            float4 w1 = *reinterpret_cast<const float4*>(W + (c4 * 4 + 1) * 64 + colm);
            float4 w2 = *reinterpret_cast<const float4*>(W + (c4 * 4 + 2) * 64 + colm);
            float4 w3 = *reinterpret_cast<const float4*>(W + (c4 * 4 + 3) * 64 + colm);
            #pragma unroll
            for (int r = 0; r < 8; r++) {
                float4 xv = *reinterpret_cast<const float4*>(xs + (rs * 8 + r) * 64 + c4 * 4);
                acc[r][0] = fmaf(xv.x, w0.x, fmaf(xv.y, w1.x, fmaf(xv.z, w2.x, fmaf(xv.w, w3.x, acc[r][0]))));
                acc[r][1] = fmaf(xv.x, w0.y, fmaf(xv.y, w1.y, fmaf(xv.z, w2.y, fmaf(xv.w, w3.y, acc[r][1]))));
                acc[r][2] = fmaf(xv.x, w0.z, fmaf(xv.y, w1.z, fmaf(xv.z, w2.z, fmaf(xv.w, w3.z, acc[r][2]))));
                acc[r][3] = fmaf(xv.x, w0.w, fmaf(xv.y, w1.w, fmaf(xv.z, w2.w, fmaf(xv.w, w3.w, acc[r][3]))));
            }
        }
        #pragma unroll
        for (int r = 0; r < 8; r++) {
            float4 v;
            v.x = acc[r][0]; v.y = acc[r][1]; v.z = acc[r][2]; v.w = acc[r][3];
            if (mat == 3) {
                v.x = expf(-expf(v.x)); v.y = expf(-expf(v.y));
                v.z = expf(-expf(v.z)); v.w = expf(-expf(v.w));
            }
            *reinterpret_cast<float4*>(dst + (rs * 8 + r) * 64 + colm) = v;
        }
    }
    __syncthreads();

    int w = tid >> 5;
    int lane = tid & 31;
    int ci = w >> 1;
    int h = w & 1;
    int b = r0 >> 12;
    int bh = b * Hq + h;
    int tloc = r0 & (Tq - 1);
    int c = (tloc >> 3) + ci;
    int col = h * 32;

    float ub[Kq];
    #pragma unroll
    for (int kk = 0; kk < Kq; kk++) ub[kk] = uL[col + kk];
    float Z[Kq];
    #pragma unroll
    for (int i = 0; i < Kq; i++) Z[i] = 0.f;
    float D = 1.f;
    int base = (bh * Tq + tloc + ci * CSq) * Kq + lane;

    #pragma unroll
    for (int t = 0; t < CSq; t++) {
        const float* rrow = sm_r + (ci * 8 + t) * 64 + col;
        const float* krow = sm_k + (ci * 8 + t) * 64 + col;
        const float* wrow = sm_w + (ci * 8 + t) * 64 + col;
        float vvv = sm_v[(ci * 8 + t) * 64 + col + lane];
        float rl = rrow[lane];
        float wl = wrow[lane];
        g_rt[base + t * Kq] = rl * D;
        float o0 = 0.f, o1 = 0.f;
        #pragma unroll
        for (int kk = 0; kk < Kq; kk += 2) {
            float rk0 = rrow[kk];
            float kx0 = krow[kk];
            float wk0 = wrow[kk];
            float rk1 = rrow[kk + 1];
            float kx1 = krow[kk + 1];
            float wk1 = wrow[kk + 1];
            float kvv0 = kx0 * vvv;
            float kvv1 = kx1 * vvv;
            o0 = fmaf(rk0, fmaf(ub[kk], kvv0, Z[kk]), o0);
            o1 = fmaf(rk1, fmaf(ub[kk + 1], kvv1, Z[kk + 1]), o1);
            Z[kk]     = fmaf(wk0, Z[kk], kvv0);
            Z[kk + 1] = fmaf(wk1, Z[kk + 1], kvv1);
        }
        g_ol[base + t * Kq] = o0 + o1;
        D *= wl;
    }
    g_Wc[(bh * NCH + c) * Kq + lane] = D;
    int tb = ((bh * NCH + c) * Kq) * Kq + lane;
    #pragma unroll
    for (int kk = 0; kk < Kq; kk++) g_Tc[tb + kk * Kq] = Z[kk];
}

// ---------------- parallel affine-scan chunk combine ----------------
#define GC (NCH / 32)
__global__ void __launch_bounds__(1024) chunk_combine_kernel() {
    int blk = blockIdx.x;
    int bh = blk >> 5;
    int kk = blk & 31;
    int tid = threadIdx.x;
    int g = tid >> 5;
    int vv = tid & 31;

    float a[GC], b[GC];
    #pragma unroll
    for (int j = 0; j < GC; j++) {
        int c = g * GC + j;
        a[j] = g_Wc[(bh * NCH + c) * Kq + kk];
        b[j] = g_Tc[((bh * NCH + c) * Kq + kk) * Kq + vv];
    }
    float A = 1.f, Bv = 0.f;
    #pragma unroll
    for (int j = 0; j < GC; j++) {
        Bv = fmaf(a[j], Bv, b[j]);
        A *= a[j];
    }
    __shared__ float sA[32 * 32];
    __shared__ float sB[32 * 32];
    sA[g * 32 + vv] = A;
    sB[g * 32 + vv] = Bv;
    __syncthreads();
    #pragma unroll
    for (int d = 1; d < 32; d <<= 1) {
        float cA = sA[g * 32 + vv];
        float cB = sB[g * 32 + vv];
        float pA = 1.f, pB = 0.f;
        if (g >= d) {
            pA = sA[(g - d) * 32 + vv];
            pB = sB[(g - d) * 32 + vv];
        }
        __syncthreads();
        sA[g * 32 + vv] = cA * pA;
        sB[g * 32 + vv] = fmaf(cA, pB, cB);
        __syncthreads();
    }
    float s = (g == 0) ? 0.f : sB[(g - 1) * 32 + vv];
    #pragma unroll
    for (int j = 0; j < GC; j++) {
        int c = g * GC + j;
        g_Sc[((bh * NCH + c) * Kq + kk) * Kq + vv] = s;
        s = fmaf(a[j], s, b[j]);
    }
}

// ---------------- fused: o = ol + r~.Sc ; y = o@Wo ; x += y ; optional fp16 ----------------
// block = (b, 64-row group), 512 threads, 16 warps; warp -> (chunk ci, head h).
// S register-resident (32/lane); rv/ol batch-preloaded (MLP 16). smem 32KB.
__global__ void __launch_bounds__(512) post_kernel(const float* __restrict__ Wo, int do_split) {
    __shared__ float Wos[4096];
    __shared__ float os[4096];
    int tid = threadIdx.x;
    int bb = blockIdx.x;
    int b = bb >> 6;
    int cg = bb & 63;
    int c0 = cg * 8;

    #pragma unroll
    for (int i = tid; i < 1024; i += 512)
        reinterpret_cast<float4*>(Wos)[i] = reinterpret_cast<const float4*>(Wo)[i];

    int w = tid >> 5;        // 0..15
    int lane = tid & 31;
    int ci = w >> 1;         // 0..7
    int h = w & 1;
    int bh = b * 2 + h;
    int c = c0 + ci;

    // batch preload: 8 (rv, o) pairs + 32 S values, all independent
    float rv8[8], o8[8];
    int base = (bh * Tq + cg * 64 + ci * 8) * Kq + lane;
    #pragma unroll
    for (int j = 0; j < 8; j++) {
        rv8[j] = g_rt[base + j * Kq];
        o8[j]  = g_ol[base + j * Kq];
    }
    float S[32];
    {
        const float* Sp = g_Sc + (size_t)(bh * NCH + c) * 1024;
        #pragma unroll
        for (int kk = 0; kk < 32; kk++) S[kk] = Sp[kk * 32 + lane];
    }
    #pragma unroll
    for (int j = 0; j < 8; j++) {
        int r = ci * 8 + j;             // 0..63 within group
        float o = o8[j];
        float rv = rv8[j];
        #pragma unroll
        for (int kk = 0; kk < 32; kk++) {
            float rk = __shfl_sync(0xffffffffu, rv, kk);
            o = fmaf(rk, S[kk], o);
        }
        os[r * 64 + h * 32 + lane] = o;
    }
    __syncthreads();

    int q = tid & 15;
    int rs = tid >> 4;       // 0..31
    int colm = q << 2;
    float acc[2][4];
    #pragma unroll
    for (int r = 0; r < 2; r++) {
        acc[r][0] = 0.f; acc[r][1] = 0.f; acc[r][2] = 0.f; acc[r][3] = 0.f;
    }
    #pragma unroll
    for (int c4 = 0; c4 < 16; c4++) {
        float4 w0 = *reinterpret_cast<const float4*>(Wos + (c4 * 4 + 0) * 64 + colm);
        float4 w1 = *reinterpret_cast<const float4*>(Wos + (c4 * 4 + 1) * 64 + colm);
        float4 w2 = *reinterpret_cast<const float4*>(Wos + (c4 * 4 + 2) * 64 + colm);
        float4 w3 = *reinterpret_cast<const float4*>(Wos + (c4 * 4 + 3) * 64 + colm);
        #pragma unroll
        for (int r = 0; r < 2; r++) {
            float4 xv = *reinterpret_cast<const float4*>(os + (rs * 2 + r) * 64 + c4 * 4);
            acc[r][0] = fmaf(xv.x, w0.x, fmaf(xv.y, w1.x, fmaf(xv.z, w2.x, fmaf(xv.w, w3.x, acc[r][0]))));
            acc[r][1] = fmaf(xv.x, w0.y, fmaf(xv.y, w1.y, fmaf(xv.z, w2.y, fmaf(xv.w, w3.y, acc[r][1]))));
            acc[r][2] = fmaf(xv.x, w0.z, fmaf(xv.y, w1.z, fmaf(xv.z, w2.z, fmaf(xv.w, w3.z, acc[r][2]))));
            acc[r][3] = fmaf(xv.x, w0.w, fmaf(xv.y, w1.w, fmaf(xv.z, w2.w, fmaf(xv.w, w3.w, acc[r][3]))));
        }
    }
    #pragma unroll
    for (int r = 0; r < 2; r++) {
        int row = b * Tq + cg * 64 + rs * 2 + r;
        size_t gidx = (size_t)row * Cq + colm;
        float4* px = reinterpret_cast<float4*>(g_x + gidx);
        float4 old = *px;
        old.x += acc[r][0]; old.y += acc[r][1]; old.z += acc[r][2]; old.w += acc[r][3];
        *px = old;
        if (do_split) {
            __half2 hh0; hh0.x = __float2half(old.x); hh0.y = __float2half(old.y);
            __half2 hh1; hh1.x = __float2half(old.z); hh1.y = __float2half(old.w);
            *reinterpret_cast<__half2*>(g_xh + gidx) = hh0;
            *reinterpret_cast<__half2*>(g_xh + gidx + 2) = hh1;
        }
    }
}

// ---------------- head GEMM: fp16 single-product, 4000 tiles across 148 CTAs ----------------
// smem: B(eh) [0,32K) | A buf0 [32K,64K) | A buf1 [64K,96K)
#define HS_TOT 98304
#define NTILES 4000

__device__ __forceinline__ void head_copy_A(uint32_t sb, int tid, int buf, int m0) {
    uint32_t dst = sb + 32768u + (uint32_t)buf * 32768u;
    const __half* srch = g_xh + (size_t)m0 * Cq;
    #pragma unroll
    for (int i = tid; i < 2048; i += 512) {
        int row = i >> 3;
        int ch = i & 7;
        uint32_t dsw = (uint32_t)(row * 128 + ((ch ^ (row & 7)) << 4));
        CP_ASYNC16(dst + dsw, srch + row * Cq + ch * 8);
    }
    CP_COMMIT();
}

__global__ void __launch_bounds__(512, 2) head_kernel(float* __restrict__ out) {
    extern __shared__ char smem[];
    const int tid = threadIdx.x;
    const int w = tid >> 5;
    const int lane = tid & 31;
    const uint32_t sb = smem_to_u32(smem);

    const int start = (int)((long long)blockIdx.x * NTILES / 148);
    const int end   = (int)((long long)(blockIdx.x + 1) * NTILES / 148);
    if (start >= end) return;

    const int g8 = lane >> 2;
    const int tig = lane & 3;
    const int wm = w >> 1;
    const int wn = w & 1;
    const int rA = (lane < 16) ? lane : (lane - 16);
    const int cA = (lane >= 16) ? 1 : 0;
    const int rB = lane & 7;
    const int cB = lane >> 3;

    int curN = -1;
    head_copy_A(sb, tid, start & 1, (start & 31) * 256);

    for (int tau = start; tau < end; tau++) {
        int n = tau >> 5;
        int mt = tau & 31;
        if (n != curN) {
            __syncthreads();
            const int4* sB_h = reinterpret_cast<const int4*>(g_eh) + (size_t)n * 256 * 8;
            #pragma unroll
            for (int i = tid; i < 2048; i += 512) {
                int row = i >> 3;
                int ch = i & 7;
                int dsw = row * 128 + ((ch ^ (row & 7)) << 4);
                *reinterpret_cast<int4*>(smem + dsw) = sB_h[i];
            }
            curN = n;
        }
        CP_WAIT0();
        __syncthreads();
        uint32_t abase = sb + 32768u + (uint32_t)((tau & 1) * 32768);

        uint32_t ah[2][4][4];
        #pragma unroll
        for (int mf = 0; mf < 2; mf++) {
            int row = wm * 32 + mf * 16 + rA;
            #pragma unroll
            for (int kc = 0; kc < 4; kc++) {
                int ch = kc * 2 + cA;
                uint32_t ad = abase + (uint32_t)(row * 128 + ((ch ^ (row & 7)) << 4));
                LDSM_X4(ah[mf][kc][0], ah[mf][kc][1], ah[mf][kc][2], ah[mf][kc][3], ad);
            }
        }
        if (tau + 1 < end) head_copy_A(sb, tid, (tau + 1) & 1, ((tau + 1) & 31) * 256);

        int n0 = n * 256;
        int m0 = mt * 256;
        #pragma unroll
        for (int nc = 0; nc < 16; nc++) {
            int nbase = wn * 128 + nc * 8;
            int rowB = nbase + rB;
            uint32_t bh[4][2];
            #pragma unroll
            for (int p = 0; p < 2; p++) {
                int ch = p * 4 + cB;
                uint32_t ad = sb + (uint32_t)(rowB * 128 + ((ch ^ (rowB & 7)) << 4));
                LDSM_X4(bh[p * 2][0], bh[p * 2][1], bh[p * 2 + 1][0], bh[p * 2 + 1][1], ad);
            }
            float c0[4] = {0.f, 0.f, 0.f, 0.f};
            float c1[4] = {0.f, 0.f, 0.f, 0.f};
            #pragma unroll
            for (int kc = 0; kc < 4; kc++) {
                MMA_FP16(c0, ah[0][kc], bh[kc]);
                MMA_FP16(c1, ah[1][kc], bh[kc]);
            }
            size_t col = (size_t)(n0 + nbase + tig * 2);
            size_t r0g = (size_t)(m0 + wm * 32 + g8);
            float* p0 = out + r0g * Vq + col;
            STG_CS_V2(p0, c0[0], c0[1]);
            STG_CS_V2(p0 + 8 * (size_t)Vq, c0[2], c0[3]);
            STG_CS_V2(p0 + 16 * (size_t)Vq, c1[0], c1[1]);
            STG_CS_V2(p0 + 24 * (size_t)Vq, c1[2], c1[3]);
        }
    }
}

extern "C" void kernel_launch(void* const* d_in, const int* in_sizes, int n_in,
                              void* d_out, int out_size) {
    const int* tokens = (const int*)d_in[0];
    const float* embed = (const float*)d_in[1];
    const float* Wr = (const float*)d_in[2];
    const float* Wk = (const float*)d_in[3];
    const float* Wv = (const float*)d_in[4];
    const float* Ww = (const float*)d_in[5];
    const float* Wo = (const float*)d_in[6];
    const float* u = (const float*)d_in[7];
    float* out = (float*)d_out;

    prep_kernel<<<8000 + 2048, 256>>>(tokens, embed);
    for (int l = 0; l < 2; l++) {
        proj_scan_kernel<<<256, 256>>>(Wr + l * 4096, Wk + l * 4096, Wv + l * 4096,
                                       Ww + l * 4096, u + l * Hq * Kq);
        chunk_combine_kernel<<<BHq * Kq, 1024>>>();
        post_kernel<<<128, 512>>>(Wo + l * 4096, l == 1);
    }
    cudaFuncSetAttribute(head_kernel, cudaFuncAttributeMaxDynamicSharedMemorySize, HS_TOT);
    head_kernel<<<148, 512, HS_TOT>>>(out);
}